// round 10
// baseline (speedup 1.0000x reference)
#include <cuda_runtime.h>
#include <math.h>
#include <stdint.h>

#define BQ 128
#define KQ 128
#define VDQ 128
#define ODQ 256
#define EQ 300
#define AQ 512
#define DQ 512
#define VQ 4000
#define TQ 32
#define XDIM 684
#define YDIM 2688    // 512 dec | 128 fbeta | 2048 hh
#define GN 2048
#define GRID_P 148
#define NSPLIT 3

// ------------------------- scratch (device globals) -------------------------
__device__ float g_att1[(size_t)BQ * KQ * AQ];           // 32 MB
__device__ float g_Yp[(size_t)NSPLIT * BQ * YDIM];
__device__ float g_Yhh[BQ * GN];
__device__ float g_h[BQ * DQ];
__device__ float g_c[BQ * DQ];
__device__ float g_awe[BQ * VDQ];
__device__ float g_init[BQ * (VDQ + ODQ)];
__device__ float g_Gv[(size_t)VQ * GN];                  // 32.8 MB
__device__ float g_Gref[BQ * GN];
__device__ float g_Ginit[GN];
__device__ float g_hstore[(size_t)TQ * BQ * DQ];
__device__ float g_predsT[(size_t)TQ * BQ * VQ];         // 64 MB
__device__ unsigned char g_mask[BQ * KQ];
__device__ int g_perm[TQ * BQ];
__device__ int g_nact;
__device__ unsigned g_cnt[8];
__device__ unsigned g_era = 0;
__device__ unsigned g_done = 0;

typedef unsigned long long ull;
__device__ __forceinline__ ull pk2(float x, float y) {
    ull r; asm("mov.b64 %0,{%1,%2};" : "=l"(r) : "f"(x), "f"(y)); return r;
}
__device__ __forceinline__ void fma2(ull& d, ull a, ull b) {
    asm("fma.rn.f32x2 %0,%1,%2,%0;" : "+l"(d) : "l"(a), "l"(b));
}
__device__ __forceinline__ float lo32(ull v) { return __uint_as_float((unsigned)v); }
__device__ __forceinline__ float hi32(ull v) { return __uint_as_float((unsigned)(v >> 32)); }
__device__ __forceinline__ float sigf(float x) { return 1.f / (1.f + expf(-x)); }

// two-level hierarchical grid barrier:
// arrive: release-RED into counter[bid&7] (<=19 serialized arrivals each)
// block 0: acquire-spin all 8 counters, publish monotonic era (release)
// others: acquire-spin on era (single read-shared line)
__device__ __forceinline__ void grid_bar(unsigned round, int bid)
{
    __syncthreads();
    if (threadIdx.x == 0) {
        asm volatile("red.release.gpu.global.add.u32 [%0], %1;"
                     :: "l"(&g_cnt[bid & 7]), "r"(1u) : "memory");
        if (bid == 0) {
            #pragma unroll
            for (int c = 0; c < 8; c++) {
                unsigned tgt = round * ((c < 4) ? 19u : 18u);
                unsigned v;
                do {
                    asm volatile("ld.acquire.gpu.global.u32 %0, [%1];"
                                 : "=r"(v) : "l"(&g_cnt[c]) : "memory");
                } while (v < tgt);
            }
            asm volatile("st.release.gpu.global.u32 [%0], %1;"
                         :: "l"(&g_era), "r"(round) : "memory");
        } else {
            unsigned v;
            do {
                asm volatile("ld.acquire.gpu.global.u32 %0, [%1];"
                             : "=r"(v) : "l"(&g_era) : "memory");
            } while (v < round);
        }
    }
    __syncthreads();
}

__device__ __forceinline__ float4 ld4g_ro(const float* base, int k, int limit) {
    if (k + 4 <= limit) return __ldg((const float4*)(base + k));
    float4 v = make_float4(0.f, 0.f, 0.f, 0.f);
    if (k + 0 < limit) v.x = __ldg(base + k + 0);
    if (k + 1 < limit) v.y = __ldg(base + k + 1);
    if (k + 2 < limit) v.z = __ldg(base + k + 2);
    if (k + 3 < limit) v.w = __ldg(base + k + 3);
    return v;
}

// ---------------- fused precompute: mask | init | Ginit ----------------------
__global__ void fused_pre(const float* __restrict__ obj,
                          const float* __restrict__ center,
                          const float* __restrict__ xyz,
                          const float* __restrict__ enc,
                          const float* __restrict__ ref_obj,
                          const float* __restrict__ init_emb,
                          const float* __restrict__ Wih,
                          float* __restrict__ out_mask)
{
    int bid = blockIdx.x, tid = threadIdx.x;
    if (bid < 128) {
        __shared__ float ds[KQ];
        __shared__ float dk[KQ];
        int b = bid, k = tid;
        const float INF = __int_as_float(0x7f800000);
        float d = INF; bool om = false;
        if (k < KQ) {
            float s0 = obj[(b * KQ + k) * 2];
            float s1 = obj[(b * KQ + k) * 2 + 1];
            om = (1.f / (1.f + expf(s0 - s1))) > 0.75f;
            float dx = center[b * 3 + 0] - xyz[(b * KQ + k) * 3 + 0];
            float dy = center[b * 3 + 1] - xyz[(b * KQ + k) * 3 + 1];
            float dz = center[b * 3 + 2] - xyz[(b * KQ + k) * 3 + 2];
            float dist = sqrtf(dx * dx + dy * dy + dz * dz);
            d = om ? dist : INF;
            ds[k] = d; dk[k] = d;
        }
        __syncthreads();
        for (int sz = 2; sz <= KQ; sz <<= 1) {
            for (int j = sz >> 1; j > 0; j >>= 1) {
                if (k < KQ) {
                    int ixj = k ^ j;
                    if (ixj > k) {
                        bool up = ((k & sz) == 0);
                        float a = ds[k], bb = ds[ixj];
                        if ((a > bb) == up) { ds[k] = bb; ds[ixj] = a; }
                    }
                }
                __syncthreads();
            }
        }
        if (k < KQ) {
            float maxd = ds[15];
            bool msk = om && (dk[k] <= maxd);
            g_mask[b * KQ + k] = msk ? 1 : 0;
            out_mask[b * KQ + k] = msk ? 1.f : 0.f;
        }
    } else if (bid < 256) {
        int b = bid - 128;
        if (tid < VDQ) {
            float s = 0.f;
            const float* eb = enc + (size_t)b * KQ * VDQ;
            #pragma unroll 4
            for (int k = 0; k < KQ; k++) s += eb[k * VDQ + tid];
            g_init[b * (VDQ + ODQ) + tid] = s * (1.f / (float)KQ);
        }
        g_init[b * (VDQ + ODQ) + VDQ + tid] = ref_obj[b * ODQ + tid];
    } else {
        int r = (bid - 256) * 256 + tid;
        const float* wr = Wih + (size_t)r * XDIM;
        float s = 0.f;
        #pragma unroll 4
        for (int k = 0; k < EQ; k++) s += init_emb[k] * wr[k];
        g_Ginit[r] = s;
    }
}

// ---------------- build active-row permutation for fc ------------------------
__global__ void build_perm(const int* __restrict__ lang_len)
{
    __shared__ unsigned cnt;
    int tid = threadIdx.x;
    if (tid == 0) cnt = 0;
    __syncthreads();
    for (int r = tid; r < TQ * BQ; r += 256) {
        int t = r >> 7, b = r & 127;
        if (t < lang_len[b]) {
            unsigned p = atomicAdd(&cnt, 1u);
            g_perm[p] = r;
        }
    }
    __syncthreads();
    if (tid == 0) g_nact = (int)cnt;
}

// ------------------------- init h0/c0 fused GEMM -----------------------------
__global__ void init_hc(const float* __restrict__ Wh, const float* __restrict__ bh,
                        const float* __restrict__ Wc, const float* __restrict__ bc)
{
    const int K = VDQ + ODQ;
    __shared__ float As[16 * 32];
    __shared__ float Bs[16 * 64];
    int tid = threadIdx.x;
    int m0 = blockIdx.y * 32;
    int n0 = blockIdx.x * 64;
    const float* Bp; const float* bias; float* out; int col;
    if (n0 < 512) { Bp = Wh; bias = bh; out = g_h; col = n0; }
    else          { Bp = Wc; bias = bc; out = g_c; col = n0 - 512; }

    int tx = tid & 15, ty = tid >> 4;
    ull acc[2][2] = {{0ull, 0ull}, {0ull, 0ull}};

    for (int k0 = 0; k0 < K; k0 += 16) {
        if (tid < 128) {
            int m = tid >> 2, kq = (tid & 3) * 4;
            float4 v = *(const float4*)&g_init[(m0 + m) * K + k0 + kq];
            As[(kq + 0) * 32 + m] = v.x; As[(kq + 1) * 32 + m] = v.y;
            As[(kq + 2) * 32 + m] = v.z; As[(kq + 3) * 32 + m] = v.w;
        }
        {
            int n = tid >> 2, kq = (tid & 3) * 4;
            float4 v = *(const float4*)&Bp[(size_t)(col + n) * K + k0 + kq];
            Bs[(kq + 0) * 64 + n] = v.x; Bs[(kq + 1) * 64 + n] = v.y;
            Bs[(kq + 2) * 64 + n] = v.z; Bs[(kq + 3) * 64 + n] = v.w;
        }
        __syncthreads();
        #pragma unroll
        for (int kk = 0; kk < 16; kk++) {
            float2 a = *(const float2*)&As[kk * 32 + ty * 2];
            ull a0 = pk2(a.x, a.x), a1 = pk2(a.y, a.y);
            const ull* bp = (const ull*)&Bs[kk * 64 + tx * 4];
            ull b01 = bp[0], b23 = bp[1];
            fma2(acc[0][0], a0, b01); fma2(acc[0][1], a0, b23);
            fma2(acc[1][0], a1, b01); fma2(acc[1][1], a1, b23);
        }
        __syncthreads();
    }
    #pragma unroll
    for (int i = 0; i < 2; i++) {
        int m = m0 + ty * 2 + i;
        int nb = col + tx * 4;
        float* cr = out + m * DQ + nb;
        cr[0] = lo32(acc[i][0]) + bias[nb + 0];
        cr[1] = hi32(acc[i][0]) + bias[nb + 1];
        cr[2] = lo32(acc[i][1]) + bias[nb + 2];
        cr[3] = hi32(acc[i][1]) + bias[nb + 3];
    }
}

// ------------- gemm128: C[M,N] = A[M,:K] @ B[N,:K]^T (+bias) -----------------
__global__ void __launch_bounds__(256)
gemm128(const float* __restrict__ A, int lda,
        const float* __restrict__ B, int ldb,
        const float* __restrict__ bias, float* __restrict__ C, int ldc,
        int M, int N, int K,
        const int* __restrict__ perm, const int* __restrict__ nact_p)
{
    __shared__ ull As2[16 * 128];    // 16 KB (duplicated packed)
    __shared__ float Bs[16 * 128];   // 8 KB
    int tid = threadIdx.x;
    int m0 = blockIdx.y * 128, n0 = blockIdx.x * 128;
    int Meff = M;
    if (nact_p) { Meff = *nact_p; if (m0 >= Meff) return; }

    int lr = tid >> 1, lk = (tid & 1) * 8;
    int arow = m0 + lr; if (arow >= Meff) arow = Meff - 1;
    int aidx = perm ? perm[arow] : arow;
    int brow = n0 + lr; if (brow >= N) brow = N - 1;
    const float* Ap = A + (size_t)aidx * lda;
    const float* Bp = B + (size_t)brow * ldb;
    int tx = tid & 15, ty = tid >> 4;

    ull acc[8][4];
    #pragma unroll
    for (int i = 0; i < 8; i++)
        #pragma unroll
        for (int p = 0; p < 4; p++) acc[i][p] = 0ull;

    float4 ra0 = ld4g_ro(Ap, lk, K),     ra1 = ld4g_ro(Ap, lk + 4, K);
    float4 rb0 = ld4g_ro(Bp, lk, K),     rb1 = ld4g_ro(Bp, lk + 4, K);

    for (int k0 = 0; k0 < K; k0 += 16) {
        As2[(lk + 0) * 128 + lr] = pk2(ra0.x, ra0.x);
        As2[(lk + 1) * 128 + lr] = pk2(ra0.y, ra0.y);
        As2[(lk + 2) * 128 + lr] = pk2(ra0.z, ra0.z);
        As2[(lk + 3) * 128 + lr] = pk2(ra0.w, ra0.w);
        As2[(lk + 4) * 128 + lr] = pk2(ra1.x, ra1.x);
        As2[(lk + 5) * 128 + lr] = pk2(ra1.y, ra1.y);
        As2[(lk + 6) * 128 + lr] = pk2(ra1.z, ra1.z);
        As2[(lk + 7) * 128 + lr] = pk2(ra1.w, ra1.w);
        Bs[(lk + 0) * 128 + lr] = rb0.x; Bs[(lk + 1) * 128 + lr] = rb0.y;
        Bs[(lk + 2) * 128 + lr] = rb0.z; Bs[(lk + 3) * 128 + lr] = rb0.w;
        Bs[(lk + 4) * 128 + lr] = rb1.x; Bs[(lk + 5) * 128 + lr] = rb1.y;
        Bs[(lk + 6) * 128 + lr] = rb1.z; Bs[(lk + 7) * 128 + lr] = rb1.w;
        __syncthreads();
        int kn = k0 + 16;
        if (kn < K) {
            ra0 = ld4g_ro(Ap, kn + lk, K); ra1 = ld4g_ro(Ap, kn + lk + 4, K);
            rb0 = ld4g_ro(Bp, kn + lk, K); rb1 = ld4g_ro(Bp, kn + lk + 4, K);
        }
        #pragma unroll
        for (int kk = 0; kk < 16; kk++) {
            const ull* ap = &As2[kk * 128 + ty * 8];
            ull a0 = ap[0], a1 = ap[1], a2 = ap[2], a3 = ap[3];
            ull a4 = ap[4], a5 = ap[5], a6 = ap[6], a7 = ap[7];
            const ull* bp = (const ull*)&Bs[kk * 128 + tx * 8];
            ull b0 = bp[0], b1 = bp[1], b2 = bp[2], b3 = bp[3];
            fma2(acc[0][0], a0, b0); fma2(acc[0][1], a0, b1); fma2(acc[0][2], a0, b2); fma2(acc[0][3], a0, b3);
            fma2(acc[1][0], a1, b0); fma2(acc[1][1], a1, b1); fma2(acc[1][2], a1, b2); fma2(acc[1][3], a1, b3);
            fma2(acc[2][0], a2, b0); fma2(acc[2][1], a2, b1); fma2(acc[2][2], a2, b2); fma2(acc[2][3], a2, b3);
            fma2(acc[3][0], a3, b0); fma2(acc[3][1], a3, b1); fma2(acc[3][2], a3, b2); fma2(acc[3][3], a3, b3);
            fma2(acc[4][0], a4, b0); fma2(acc[4][1], a4, b1); fma2(acc[4][2], a4, b2); fma2(acc[4][3], a4, b3);
            fma2(acc[5][0], a5, b0); fma2(acc[5][1], a5, b1); fma2(acc[5][2], a5, b2); fma2(acc[5][3], a5, b3);
            fma2(acc[6][0], a6, b0); fma2(acc[6][1], a6, b1); fma2(acc[6][2], a6, b2); fma2(acc[6][3], a6, b3);
            fma2(acc[7][0], a7, b0); fma2(acc[7][1], a7, b1); fma2(acc[7][2], a7, b2); fma2(acc[7][3], a7, b3);
        }
        __syncthreads();
    }

    #pragma unroll
    for (int i = 0; i < 8; i++) {
        int m = m0 + ty * 8 + i;
        if (m >= Meff) continue;
        int cidx = perm ? perm[m] : m;
        float* cr = C + (size_t)cidx * ldc;
        #pragma unroll
        for (int p = 0; p < 4; p++) {
            int nn = n0 + tx * 8 + p * 2;
            if (nn < N)     cr[nn]     = lo32(acc[i][p]) + (bias ? bias[nn] : 0.f);
            if (nn + 1 < N) cr[nn + 1] = hi32(acc[i][p]) + (bias ? bias[nn + 1] : 0.f);
        }
    }
}

// ------------------------- persistent decoder loop ---------------------------
__global__ void __launch_bounds__(256)
decoder_loop(const float* __restrict__ enc,
             const float* __restrict__ Wd, const float* __restrict__ Wf,
             const float* __restrict__ Whh,
             const float* __restrict__ b_dec, const float* __restrict__ b_fbeta,
             const float* __restrict__ w_full, const float* __restrict__ b_full,
             const float* __restrict__ Wih, const float* __restrict__ b_ih,
             const float* __restrict__ b_hh,
             const int* __restrict__ lang_idx, const int* __restrict__ lang_len,
             float* __restrict__ out_alpha)
{
    __shared__ __align__(16) char sm[24576];
    int tid = threadIdx.x, bid = blockIdx.x;
    int tx = tid & 15, ty = tid >> 4;
    unsigned round = 0;

    for (int t = 0; t < TQ; t++) {
        // ======================= P1 (pipelined) =======================
        if (bid < 126) {
            ull*   As2 = (ull*)sm;               // [16][128] ulls (16 KB)
            float* Bs  = (float*)(sm + 16384);   // [16][64]  (4 KB)
            int ks = bid % 3, nt = bid / 3;
            int k0 = ks * 176;
            int nkt = (ks < 2) ? 11 : 10;
            int br = tid >> 2, bk = (tid & 3) * 4;
            int n = nt * 64 + br;
            const float* Brow;
            if (n < 512)      Brow = Wd  + (size_t)n * DQ;
            else if (n < 640) Brow = Wf  + (size_t)(n - 512) * DQ;
            else              Brow = Whh + (size_t)(n - 640) * DQ;
            int lr = tid >> 1, lk = (tid & 1) * 8;

            ull acc[8][2];
            #pragma unroll
            for (int i = 0; i < 8; i++) { acc[i][0] = 0ull; acc[i][1] = 0ull; }

            float4 pa0 = __ldcg((const float4*)&g_h[lr * DQ + k0 + lk]);
            float4 pa1 = __ldcg((const float4*)&g_h[lr * DQ + k0 + lk + 4]);
            float4 pb  = __ldg((const float4*)&Brow[k0 + bk]);

            for (int kt = 0; kt < nkt; kt++) {
                As2[(lk + 0) * 128 + lr] = pk2(pa0.x, pa0.x);
                As2[(lk + 1) * 128 + lr] = pk2(pa0.y, pa0.y);
                As2[(lk + 2) * 128 + lr] = pk2(pa0.z, pa0.z);
                As2[(lk + 3) * 128 + lr] = pk2(pa0.w, pa0.w);
                As2[(lk + 4) * 128 + lr] = pk2(pa1.x, pa1.x);
                As2[(lk + 5) * 128 + lr] = pk2(pa1.y, pa1.y);
                As2[(lk + 6) * 128 + lr] = pk2(pa1.z, pa1.z);
                As2[(lk + 7) * 128 + lr] = pk2(pa1.w, pa1.w);
                Bs[(bk + 0) * 64 + br] = pb.x; Bs[(bk + 1) * 64 + br] = pb.y;
                Bs[(bk + 2) * 64 + br] = pb.z; Bs[(bk + 3) * 64 + br] = pb.w;
                __syncthreads();
                if (kt + 1 < nkt) {
                    int k = k0 + (kt + 1) * 16;
                    pa0 = __ldcg((const float4*)&g_h[lr * DQ + k + lk]);
                    pa1 = __ldcg((const float4*)&g_h[lr * DQ + k + lk + 4]);
                    pb  = __ldg((const float4*)&Brow[k + bk]);
                }
                #pragma unroll
                for (int kk = 0; kk < 16; kk++) {
                    const ull* ap = &As2[kk * 128 + ty * 8];
                    ull a0 = ap[0], a1 = ap[1], a2 = ap[2], a3 = ap[3];
                    ull a4 = ap[4], a5 = ap[5], a6 = ap[6], a7 = ap[7];
                    const ull* bp = (const ull*)&Bs[kk * 64 + tx * 4];
                    ull b0 = bp[0], b1 = bp[1];
                    fma2(acc[0][0], a0, b0); fma2(acc[0][1], a0, b1);
                    fma2(acc[1][0], a1, b0); fma2(acc[1][1], a1, b1);
                    fma2(acc[2][0], a2, b0); fma2(acc[2][1], a2, b1);
                    fma2(acc[3][0], a3, b0); fma2(acc[3][1], a3, b1);
                    fma2(acc[4][0], a4, b0); fma2(acc[4][1], a4, b1);
                    fma2(acc[5][0], a5, b0); fma2(acc[5][1], a5, b1);
                    fma2(acc[6][0], a6, b0); fma2(acc[6][1], a6, b1);
                    fma2(acc[7][0], a7, b0); fma2(acc[7][1], a7, b1);
                }
                __syncthreads();
            }
            float* Cp = g_Yp + (size_t)ks * BQ * YDIM + nt * 64;
            #pragma unroll
            for (int i = 0; i < 8; i++) {
                int m = ty * 8 + i;
                float4 o = make_float4(lo32(acc[i][0]), hi32(acc[i][0]),
                                       lo32(acc[i][1]), hi32(acc[i][1]));
                __stcg((float4*)&Cp[(size_t)m * YDIM + tx * 4], o);
            }
        }
        grid_bar(++round, bid);

        // ======================= P2 =======================
        if (bid < 128) {
            int b = bid;
            float* pool    = (float*)sm;
            float* att2_s  = pool;
            float* w_s     = pool + 512;
            float* att_s   = pool + 1024;
            float* red     = pool + 1152;
            float* alpha_s = pool + 1280;
            float* part    = pool + 1408;

            #pragma unroll
            for (int a = tid; a < AQ; a += 256) {
                float v = b_dec[a];
                #pragma unroll
                for (int s = 0; s < NSPLIT; s++)
                    v += __ldcg(&g_Yp[((size_t)s * BQ + b) * YDIM + a]);
                att2_s[a] = v;
                w_s[a] = w_full[a];
            }
            __syncthreads();

            int warp = tid >> 5, lane = tid & 31;
            #pragma unroll 2
            for (int k = warp; k < KQ; k += 8) {
                const float* a1 = g_att1 + ((size_t)b * KQ + k) * AQ;
                float s = 0.f;
                #pragma unroll
                for (int c = 0; c < 4; c++) {
                    int base = c * 128 + lane * 4;
                    float4 v = __ldg((const float4*)&a1[base]);
                    s += fmaxf(v.x + att2_s[base + 0], 0.f) * w_s[base + 0];
                    s += fmaxf(v.y + att2_s[base + 1], 0.f) * w_s[base + 1];
                    s += fmaxf(v.z + att2_s[base + 2], 0.f) * w_s[base + 2];
                    s += fmaxf(v.w + att2_s[base + 3], 0.f) * w_s[base + 3];
                }
                #pragma unroll
                for (int o = 16; o; o >>= 1) s += __shfl_down_sync(0xffffffffu, s, o);
                if (lane == 0) att_s[k] = s + b_full[0];
            }
            __syncthreads();

            if (tid < KQ)
                red[tid] = g_mask[b * KQ + tid] ? att_s[tid]
                                                : -__int_as_float(0x7f800000);
            __syncthreads();
            for (int s = 64; s > 0; s >>= 1) {
                if (tid < s) red[tid] = fmaxf(red[tid], red[tid + s]);
                __syncthreads();
            }
            float mx = red[0];
            if (isinf(mx)) mx = 0.f;
            __syncthreads();
            if (tid < KQ) {
                float e = g_mask[b * KQ + tid] ? expf(att_s[tid] - mx) : 0.f;
                alpha_s[tid] = e;
                red[tid] = e;
            }
            __syncthreads();
            for (int s = 64; s > 0; s >>= 1) {
                if (tid < s) red[tid] += red[tid + s];
                __syncthreads();
            }
            float dsum = red[0];
            float inv = (dsum > 0.f) ? 1.f / fmaxf(dsum, 1e-30f) : 0.f;
            __syncthreads();
            if (tid < KQ) alpha_s[tid] *= inv;
            __syncthreads();

            {
                int v = tid & (VDQ - 1), q = tid >> 7;
                const float* eb = enc + (size_t)b * KQ * VDQ;
                float s = 0.f;
                #pragma unroll 8
                for (int k = q * 64; k < q * 64 + 64; k++)
                    s += alpha_s[k] * __ldg(&eb[k * VDQ + v]);
                part[tid] = s;
            }
            __syncthreads();

            bool active = (t < lang_len[b]);
            if (tid < VDQ) {
                float aw = part[tid] + part[tid + 128];
                float gv = b_fbeta[tid];
                #pragma unroll
                for (int s = 0; s < NSPLIT; s++)
                    gv += __ldcg(&g_Yp[((size_t)s * BQ + b) * YDIM + 512 + tid]);
                __stcg(&g_awe[b * VDQ + tid], aw * sigf(gv));
                out_alpha[(size_t)b * TQ * KQ + (size_t)t * KQ + tid]
                    = active ? alpha_s[tid] : 0.f;
            }

            // fused Yhh partial reduction (same b)
            {
                int col = tid * 8;
                float4 s0 = make_float4(0.f, 0.f, 0.f, 0.f);
                float4 s1 = make_float4(0.f, 0.f, 0.f, 0.f);
                #pragma unroll
                for (int s = 0; s < NSPLIT; s++) {
                    const float* p = g_Yp + ((size_t)s * BQ + b) * YDIM + 640 + col;
                    float4 v0 = __ldcg((const float4*)p);
                    float4 v1 = __ldcg((const float4*)(p + 4));
                    s0.x += v0.x; s0.y += v0.y; s0.z += v0.z; s0.w += v0.w;
                    s1.x += v1.x; s1.y += v1.y; s1.z += v1.z; s1.w += v1.w;
                }
                __stcg((float4*)&g_Yhh[b * GN + col], s0);
                __stcg((float4*)&g_Yhh[b * GN + col + 4], s1);
            }
        }
        grid_bar(++round, bid);

        // ======================= P3 (pipelined) =======================
        if (bid < 128) {
            float* As  = (float*)sm;             // [16][64]
            float* Bs3 = (float*)(sm + 4096);    // [16][32]
            int m0 = (bid & 1) * 64;
            int jt = bid >> 1;
            int n0v = jt * 32;
            int am = tid >> 2, ak4 = (tid & 3) * 4;
            int vr = tid >> 3, kb = (tid & 7) * 2;
            int vcol = n0v + vr;
            int wr = (vcol & 3) * 512 + (vcol >> 2);
            const float* Brow = Wih + (size_t)wr * XDIM + EQ;

            int jx = tid & 7, my = tid >> 3;
            ull acc[2][2] = {{0ull, 0ull}, {0ull, 0ull}};

            float4 pa = __ldcg((const float4*)&g_awe[(m0 + am) * VDQ + ak4]);
            float2 pb = *(const float2*)&Brow[kb];

            for (int kt = 0; kt < 8; kt++) {
                As[(ak4 + 0) * 64 + am] = pa.x; As[(ak4 + 1) * 64 + am] = pa.y;
                As[(ak4 + 2) * 64 + am] = pa.z; As[(ak4 + 3) * 64 + am] = pa.w;
                Bs3[(kb + 0) * 32 + vr] = pb.x;
                Bs3[(kb + 1) * 32 + vr] = pb.y;
                __syncthreads();
                if (kt + 1 < 8) {
                    int k = (kt + 1) * 16;
                    pa = __ldcg((const float4*)&g_awe[(m0 + am) * VDQ + k + ak4]);
                    pb = *(const float2*)&Brow[k + kb];
                }
                #pragma unroll
                for (int kk = 0; kk < 16; kk++) {
                    float2 a2 = *(const float2*)&As[kk * 64 + my * 2];
                    const ull* bp = (const ull*)&Bs3[kk * 32 + jx * 4];
                    ull b01 = bp[0], b23 = bp[1];
                    ull pa0 = pk2(a2.x, a2.x), pa1 = pk2(a2.y, a2.y);
                    fma2(acc[0][0], pa0, b01); fma2(acc[0][1], pa0, b23);
                    fma2(acc[1][0], pa1, b01); fma2(acc[1][1], pa1, b23);
                }
                __syncthreads();
            }

            int j = jt * 8 + jx;
            float bi_i = b_ih[j]        + b_hh[j];
            float bi_f = b_ih[512 + j]  + b_hh[512 + j];
            float bi_g = b_ih[1024 + j] + b_hh[1024 + j];
            float bi_o = b_ih[1536 + j] + b_hh[1536 + j];
            #pragma unroll
            for (int i = 0; i < 2; i++) {
                int b = m0 + my * 2 + i;
                const float* Gv = (t == 0) ? g_Ginit
                    : g_Gv + (size_t)__ldg(&lang_idx[b * TQ + (t - 1)]) * GN;
                float gi = lo32(acc[i][0]) + Gv[j]        + g_Gref[b * GN + j]        + __ldcg(&g_Yhh[b * GN + j])        + bi_i;
                float gf = hi32(acc[i][0]) + Gv[512 + j]  + g_Gref[b * GN + 512 + j]  + __ldcg(&g_Yhh[b * GN + 512 + j])  + bi_f;
                float gg = lo32(acc[i][1]) + Gv[1024 + j] + g_Gref[b * GN + 1024 + j] + __ldcg(&g_Yhh[b * GN + 1024 + j]) + bi_g;
                float go = hi32(acc[i][1]) + Gv[1536 + j] + g_Gref[b * GN + 1536 + j] + __ldcg(&g_Yhh[b * GN + 1536 + j]) + bi_o;
                float c_old = __ldcg(&g_c[b * DQ + j]);
                float cn = sigf(gf) * c_old + sigf(gi) * tanhf(gg);
                float hn = sigf(go) * tanhf(cn);
                bool act = t < lang_len[b];
                float h_prev = __ldcg(&g_h[b * DQ + j]);
                float h_out = act ? hn : h_prev;
                if (act) {
                    __stcg(&g_c[b * DQ + j], cn);
                    __stcg(&g_h[b * DQ + j], hn);
                }
                g_hstore[((size_t)t * BQ + b) * DQ + j] = h_out;
            }
        }
        if (t != TQ - 1) grid_bar(++round, bid);
    }

    // done protocol (reset all barrier state for next graph replay)
    __syncthreads();
    __threadfence();
    if (tid == 0) {
        asm volatile("red.release.gpu.global.add.u32 [%0], %1;"
                     :: "l"(&g_done), "r"(1u) : "memory");
        if (bid == 0) {
            unsigned v;
            do {
                asm volatile("ld.acquire.gpu.global.u32 %0, [%1];"
                             : "=r"(v) : "l"(&g_done) : "memory");
            } while (v < (unsigned)GRID_P);
            #pragma unroll
            for (int c = 0; c < 8; c++)
                asm volatile("st.global.cg.u32 [%0], %1;" :: "l"(&g_cnt[c]), "r"(0u) : "memory");
            asm volatile("st.global.cg.u32 [%0], %1;" :: "l"(&g_era), "r"(0u) : "memory");
            __threadfence();
            asm volatile("st.release.gpu.global.u32 [%0], %1;"
                         :: "l"(&g_done), "r"(0u) : "memory");
        }
    }
}

// ---------- final: mask + transpose [T,B,V] -> [B,V,T] ------------------------
__global__ void transpose_preds(const int* __restrict__ lang_len,
                                float* __restrict__ out)
{
    __shared__ float tile[32][33];
    int b = blockIdx.x;
    int v0 = blockIdx.y * 32;
    int tx = threadIdx.x, ty = threadIdx.y;
    float s = 0.f;
    if (ty < lang_len[b])
        s = g_predsT[(size_t)ty * BQ * VQ + (size_t)b * VQ + v0 + tx];
    tile[ty][tx] = s;
    __syncthreads();
    out[(size_t)b * VQ * TQ + (size_t)(v0 + ty) * TQ + tx] = tile[tx][ty];
}

// ------------------------- launch ---------------------------------------------
extern "C" void kernel_launch(void* const* d_in, const int* in_sizes, int n_in,
                              void* d_out, int out_size)
{
    const float* enc       = (const float*)d_in[0];
    const float* ref_obj   = (const float*)d_in[1];
    const float* obj_sc    = (const float*)d_in[2];
    const float* center    = (const float*)d_in[3];
    const float* xyz       = (const float*)d_in[4];
    const int*   lang_idx  = (const int*)d_in[5];
    const int*   lang_len  = (const int*)d_in[6];
    const float* emb_tab   = (const float*)d_in[7];
    const float* init_emb  = (const float*)d_in[8];
    const float* W_enc_att = (const float*)d_in[9];
    const float* b_enc_att = (const float*)d_in[10];
    const float* W_dec_att = (const float*)d_in[11];
    const float* b_dec_att = (const float*)d_in[12];
    const float* w_full    = (const float*)d_in[13];
    const float* b_full    = (const float*)d_in[14];
    const float* W_ih      = (const float*)d_in[15];
    const float* b_ih      = (const float*)d_in[16];
    const float* W_hh      = (const float*)d_in[17];
    const float* b_hh      = (const float*)d_in[18];
    const float* W_init_h  = (const float*)d_in[19];
    const float* b_init_h  = (const float*)d_in[20];
    const float* W_init_c  = (const float*)d_in[21];
    const float* b_init_c  = (const float*)d_in[22];
    const float* W_fbeta   = (const float*)d_in[23];
    const float* b_fbeta   = (const float*)d_in[24];
    const float* W_fc      = (const float*)d_in[25];
    const float* b_fc      = (const float*)d_in[26];

    float* out       = (float*)d_out;
    float* out_alpha = out + (size_t)BQ * VQ * TQ;
    float* out_mask  = out_alpha + (size_t)BQ * TQ * KQ;

    float *p_att1, *p_Gv, *p_Gref, *p_hstore, *p_predsT;
    int *p_perm, *p_nact;
    cudaGetSymbolAddress((void**)&p_att1,   g_att1);
    cudaGetSymbolAddress((void**)&p_Gv,     g_Gv);
    cudaGetSymbolAddress((void**)&p_Gref,   g_Gref);
    cudaGetSymbolAddress((void**)&p_hstore, g_hstore);
    cudaGetSymbolAddress((void**)&p_predsT, g_predsT);
    cudaGetSymbolAddress((void**)&p_perm,   g_perm);
    cudaGetSymbolAddress((void**)&p_nact,   g_nact);

    fused_pre<<<264, 256>>>(obj_sc, center, xyz, enc, ref_obj, init_emb,
                            W_ih, out_mask);
    init_hc<<<dim3(16, 4), 256>>>(W_init_h, b_init_h, W_init_c, b_init_c);
    gemm128<<<dim3(16, 1), 256>>>(ref_obj, ODQ, W_ih + EQ + VDQ, XDIM, nullptr,
                                  p_Gref, GN, BQ, GN, ODQ, nullptr, nullptr);
    gemm128<<<dim3(4, 128), 256>>>(enc, VDQ, W_enc_att, VDQ, b_enc_att,
                                   p_att1, AQ, BQ * KQ, AQ, VDQ, nullptr, nullptr);
    gemm128<<<dim3(16, 32), 256>>>(emb_tab, EQ, W_ih, XDIM, nullptr,
                                   p_Gv, GN, VQ, GN, EQ, nullptr, nullptr);
    decoder_loop<<<GRID_P, 256>>>(enc, W_dec_att, W_fbeta, W_hh,
                                  b_dec_att, b_fbeta, w_full, b_full,
                                  W_ih, b_ih, b_hh, lang_idx, lang_len,
                                  out_alpha);
    build_perm<<<1, 256>>>(lang_len);
    gemm128<<<dim3(32, 32), 256>>>(p_hstore, DQ, W_fc, DQ, b_fc,
                                   p_predsT, VQ, TQ * BQ, VQ, DQ, p_perm, p_nact);
    transpose_preds<<<dim3(BQ, VQ / 32), dim3(32, 32)>>>(lang_len, out);
}

// round 11
// speedup vs baseline: 1.6318x; 1.6318x over previous
#include <cuda_runtime.h>
#include <math.h>
#include <stdint.h>

#define BQ 128
#define KQ 128
#define VDQ 128
#define ODQ 256
#define EQ 300
#define AQ 512
#define DQ 512
#define VQ 4000
#define TQ 32
#define XDIM 684
#define YDIM 2688    // 512 dec | 128 fbeta | 2048 hh
#define GN 2048
#define GRID_P 148
#define NSPLIT 3

// ------------------------- scratch (device globals) -------------------------
__device__ float g_att1[(size_t)BQ * KQ * AQ];           // 32 MB
__device__ float g_Yp[(size_t)NSPLIT * BQ * YDIM];
__device__ float g_Yhh[BQ * GN];
__device__ float g_h[BQ * DQ];
__device__ float g_c[BQ * DQ];
__device__ float g_awe[BQ * VDQ];
__device__ float g_init[BQ * (VDQ + ODQ)];
__device__ float g_Gv[(size_t)VQ * GN];                  // 32.8 MB
__device__ float g_Gref[BQ * GN];
__device__ float g_Ginit[GN];
__device__ float g_hstore[(size_t)TQ * BQ * DQ];
__device__ float g_predsT[(size_t)TQ * BQ * VQ];         // 64 MB
__device__ unsigned char g_mask[BQ * KQ];
__device__ int g_perm[TQ * BQ];
__device__ int g_nact;
__device__ unsigned g_bar = 0;
__device__ unsigned g_done = 0;

typedef unsigned long long ull;
__device__ __forceinline__ ull pk2(float x, float y) {
    ull r; asm("mov.b64 %0,{%1,%2};" : "=l"(r) : "f"(x), "f"(y)); return r;
}
__device__ __forceinline__ void fma2(ull& d, ull a, ull b) {
    asm("fma.rn.f32x2 %0,%1,%2,%0;" : "+l"(d) : "l"(a), "l"(b));
}
__device__ __forceinline__ float lo32(ull v) { return __uint_as_float((unsigned)v); }
__device__ __forceinline__ float hi32(ull v) { return __uint_as_float((unsigned)(v >> 32)); }
__device__ __forceinline__ float sigf(float x) { return 1.f / (1.f + expf(-x)); }

// flat grid barrier (round-9 proven): release-RED arrive + acquire spin
__device__ __forceinline__ void grid_bar(unsigned target)
{
    __syncthreads();
    if (threadIdx.x == 0) {
        asm volatile("red.release.gpu.global.add.u32 [%0], %1;"
                     :: "l"(&g_bar), "r"(1u) : "memory");
        unsigned v;
        do {
            asm volatile("ld.acquire.gpu.global.u32 %0, [%1];"
                         : "=r"(v) : "l"(&g_bar) : "memory");
        } while (v < target);
    }
    __syncthreads();
}

__device__ __forceinline__ float4 ld4g_ro(const float* base, int k, int limit) {
    if (k + 4 <= limit) return __ldg((const float4*)(base + k));
    float4 v = make_float4(0.f, 0.f, 0.f, 0.f);
    if (k + 0 < limit) v.x = __ldg(base + k + 0);
    if (k + 1 < limit) v.y = __ldg(base + k + 1);
    if (k + 2 < limit) v.z = __ldg(base + k + 2);
    if (k + 3 < limit) v.w = __ldg(base + k + 3);
    return v;
}

// ---------------- fused precompute: mask | init | Ginit ----------------------
__global__ void fused_pre(const float* __restrict__ obj,
                          const float* __restrict__ center,
                          const float* __restrict__ xyz,
                          const float* __restrict__ enc,
                          const float* __restrict__ ref_obj,
                          const float* __restrict__ init_emb,
                          const float* __restrict__ Wih,
                          float* __restrict__ out_mask)
{
    int bid = blockIdx.x, tid = threadIdx.x;
    if (bid < 128) {
        __shared__ float ds[KQ];
        __shared__ float dk[KQ];
        int b = bid, k = tid;
        const float INF = __int_as_float(0x7f800000);
        float d = INF; bool om = false;
        if (k < KQ) {
            float s0 = obj[(b * KQ + k) * 2];
            float s1 = obj[(b * KQ + k) * 2 + 1];
            om = (1.f / (1.f + expf(s0 - s1))) > 0.75f;
            float dx = center[b * 3 + 0] - xyz[(b * KQ + k) * 3 + 0];
            float dy = center[b * 3 + 1] - xyz[(b * KQ + k) * 3 + 1];
            float dz = center[b * 3 + 2] - xyz[(b * KQ + k) * 3 + 2];
            float dist = sqrtf(dx * dx + dy * dy + dz * dz);
            d = om ? dist : INF;
            ds[k] = d; dk[k] = d;
        }
        __syncthreads();
        for (int sz = 2; sz <= KQ; sz <<= 1) {
            for (int j = sz >> 1; j > 0; j >>= 1) {
                if (k < KQ) {
                    int ixj = k ^ j;
                    if (ixj > k) {
                        bool up = ((k & sz) == 0);
                        float a = ds[k], bb = ds[ixj];
                        if ((a > bb) == up) { ds[k] = bb; ds[ixj] = a; }
                    }
                }
                __syncthreads();
            }
        }
        if (k < KQ) {
            float maxd = ds[15];
            bool msk = om && (dk[k] <= maxd);
            g_mask[b * KQ + k] = msk ? 1 : 0;
            out_mask[b * KQ + k] = msk ? 1.f : 0.f;
        }
    } else if (bid < 256) {
        int b = bid - 128;
        if (tid < VDQ) {
            float s = 0.f;
            const float* eb = enc + (size_t)b * KQ * VDQ;
            #pragma unroll 4
            for (int k = 0; k < KQ; k++) s += eb[k * VDQ + tid];
            g_init[b * (VDQ + ODQ) + tid] = s * (1.f / (float)KQ);
        }
        g_init[b * (VDQ + ODQ) + VDQ + tid] = ref_obj[b * ODQ + tid];
    } else {
        int r = (bid - 256) * 256 + tid;
        const float* wr = Wih + (size_t)r * XDIM;
        float s = 0.f;
        #pragma unroll 4
        for (int k = 0; k < EQ; k++) s += init_emb[k] * wr[k];
        g_Ginit[r] = s;
    }
}

// ---------------- build active-row permutation for fc ------------------------
__global__ void build_perm(const int* __restrict__ lang_len)
{
    __shared__ unsigned cnt;
    int tid = threadIdx.x;
    if (tid == 0) cnt = 0;
    __syncthreads();
    for (int r = tid; r < TQ * BQ; r += 256) {
        int t = r >> 7, b = r & 127;
        if (t < lang_len[b]) {
            unsigned p = atomicAdd(&cnt, 1u);
            g_perm[p] = r;
        }
    }
    __syncthreads();
    if (tid == 0) g_nact = (int)cnt;
}

// ------------------------- init h0/c0 fused GEMM -----------------------------
__global__ void init_hc(const float* __restrict__ Wh, const float* __restrict__ bh,
                        const float* __restrict__ Wc, const float* __restrict__ bc)
{
    const int K = VDQ + ODQ;
    __shared__ float As[16 * 32];
    __shared__ float Bs[16 * 64];
    int tid = threadIdx.x;
    int m0 = blockIdx.y * 32;
    int n0 = blockIdx.x * 64;
    const float* Bp; const float* bias; float* out; int col;
    if (n0 < 512) { Bp = Wh; bias = bh; out = g_h; col = n0; }
    else          { Bp = Wc; bias = bc; out = g_c; col = n0 - 512; }

    int tx = tid & 15, ty = tid >> 4;
    ull acc[2][2] = {{0ull, 0ull}, {0ull, 0ull}};

    for (int k0 = 0; k0 < K; k0 += 16) {
        if (tid < 128) {
            int m = tid >> 2, kq = (tid & 3) * 4;
            float4 v = *(const float4*)&g_init[(m0 + m) * K + k0 + kq];
            As[(kq + 0) * 32 + m] = v.x; As[(kq + 1) * 32 + m] = v.y;
            As[(kq + 2) * 32 + m] = v.z; As[(kq + 3) * 32 + m] = v.w;
        }
        {
            int n = tid >> 2, kq = (tid & 3) * 4;
            float4 v = *(const float4*)&Bp[(size_t)(col + n) * K + k0 + kq];
            Bs[(kq + 0) * 64 + n] = v.x; Bs[(kq + 1) * 64 + n] = v.y;
            Bs[(kq + 2) * 64 + n] = v.z; Bs[(kq + 3) * 64 + n] = v.w;
        }
        __syncthreads();
        #pragma unroll
        for (int kk = 0; kk < 16; kk++) {
            float2 a = *(const float2*)&As[kk * 32 + ty * 2];
            ull a0 = pk2(a.x, a.x), a1 = pk2(a.y, a.y);
            const ull* bp = (const ull*)&Bs[kk * 64 + tx * 4];
            ull b01 = bp[0], b23 = bp[1];
            fma2(acc[0][0], a0, b01); fma2(acc[0][1], a0, b23);
            fma2(acc[1][0], a1, b01); fma2(acc[1][1], a1, b23);
        }
        __syncthreads();
    }
    #pragma unroll
    for (int i = 0; i < 2; i++) {
        int m = m0 + ty * 2 + i;
        int nb = col + tx * 4;
        float* cr = out + m * DQ + nb;
        cr[0] = lo32(acc[i][0]) + bias[nb + 0];
        cr[1] = hi32(acc[i][0]) + bias[nb + 1];
        cr[2] = lo32(acc[i][1]) + bias[nb + 2];
        cr[3] = hi32(acc[i][1]) + bias[nb + 3];
    }
}

// ------------- gemm128: C[M,N] = A[M,:K] @ B[N,:K]^T (+bias) -----------------
__global__ void __launch_bounds__(256)
gemm128(const float* __restrict__ A, int lda,
        const float* __restrict__ B, int ldb,
        const float* __restrict__ bias, float* __restrict__ C, int ldc,
        int M, int N, int K,
        const int* __restrict__ perm, const int* __restrict__ nact_p)
{
    __shared__ ull As2[16 * 128];    // 16 KB (duplicated packed)
    __shared__ float Bs[16 * 128];   // 8 KB
    int tid = threadIdx.x;
    int m0 = blockIdx.y * 128, n0 = blockIdx.x * 128;
    int Meff = M;
    if (nact_p) { Meff = *nact_p; if (m0 >= Meff) return; }

    int lr = tid >> 1, lk = (tid & 1) * 8;
    int arow = m0 + lr; if (arow >= Meff) arow = Meff - 1;
    int aidx = perm ? perm[arow] : arow;
    int brow = n0 + lr; if (brow >= N) brow = N - 1;
    const float* Ap = A + (size_t)aidx * lda;
    const float* Bp = B + (size_t)brow * ldb;
    int tx = tid & 15, ty = tid >> 4;

    ull acc[8][4];
    #pragma unroll
    for (int i = 0; i < 8; i++)
        #pragma unroll
        for (int p = 0; p < 4; p++) acc[i][p] = 0ull;

    float4 ra0 = ld4g_ro(Ap, lk, K),     ra1 = ld4g_ro(Ap, lk + 4, K);
    float4 rb0 = ld4g_ro(Bp, lk, K),     rb1 = ld4g_ro(Bp, lk + 4, K);

    for (int k0 = 0; k0 < K; k0 += 16) {
        As2[(lk + 0) * 128 + lr] = pk2(ra0.x, ra0.x);
        As2[(lk + 1) * 128 + lr] = pk2(ra0.y, ra0.y);
        As2[(lk + 2) * 128 + lr] = pk2(ra0.z, ra0.z);
        As2[(lk + 3) * 128 + lr] = pk2(ra0.w, ra0.w);
        As2[(lk + 4) * 128 + lr] = pk2(ra1.x, ra1.x);
        As2[(lk + 5) * 128 + lr] = pk2(ra1.y, ra1.y);
        As2[(lk + 6) * 128 + lr] = pk2(ra1.z, ra1.z);
        As2[(lk + 7) * 128 + lr] = pk2(ra1.w, ra1.w);
        Bs[(lk + 0) * 128 + lr] = rb0.x; Bs[(lk + 1) * 128 + lr] = rb0.y;
        Bs[(lk + 2) * 128 + lr] = rb0.z; Bs[(lk + 3) * 128 + lr] = rb0.w;
        Bs[(lk + 4) * 128 + lr] = rb1.x; Bs[(lk + 5) * 128 + lr] = rb1.y;
        Bs[(lk + 6) * 128 + lr] = rb1.z; Bs[(lk + 7) * 128 + lr] = rb1.w;
        __syncthreads();
        int kn = k0 + 16;
        if (kn < K) {
            ra0 = ld4g_ro(Ap, kn + lk, K); ra1 = ld4g_ro(Ap, kn + lk + 4, K);
            rb0 = ld4g_ro(Bp, kn + lk, K); rb1 = ld4g_ro(Bp, kn + lk + 4, K);
        }
        #pragma unroll
        for (int kk = 0; kk < 16; kk++) {
            const ull* ap = &As2[kk * 128 + ty * 8];
            ull a0 = ap[0], a1 = ap[1], a2 = ap[2], a3 = ap[3];
            ull a4 = ap[4], a5 = ap[5], a6 = ap[6], a7 = ap[7];
            const ull* bp = (const ull*)&Bs[kk * 128 + tx * 8];
            ull b0 = bp[0], b1 = bp[1], b2 = bp[2], b3 = bp[3];
            fma2(acc[0][0], a0, b0); fma2(acc[0][1], a0, b1); fma2(acc[0][2], a0, b2); fma2(acc[0][3], a0, b3);
            fma2(acc[1][0], a1, b0); fma2(acc[1][1], a1, b1); fma2(acc[1][2], a1, b2); fma2(acc[1][3], a1, b3);
            fma2(acc[2][0], a2, b0); fma2(acc[2][1], a2, b1); fma2(acc[2][2], a2, b2); fma2(acc[2][3], a2, b3);
            fma2(acc[3][0], a3, b0); fma2(acc[3][1], a3, b1); fma2(acc[3][2], a3, b2); fma2(acc[3][3], a3, b3);
            fma2(acc[4][0], a4, b0); fma2(acc[4][1], a4, b1); fma2(acc[4][2], a4, b2); fma2(acc[4][3], a4, b3);
            fma2(acc[5][0], a5, b0); fma2(acc[5][1], a5, b1); fma2(acc[5][2], a5, b2); fma2(acc[5][3], a5, b3);
            fma2(acc[6][0], a6, b0); fma2(acc[6][1], a6, b1); fma2(acc[6][2], a6, b2); fma2(acc[6][3], a6, b3);
            fma2(acc[7][0], a7, b0); fma2(acc[7][1], a7, b1); fma2(acc[7][2], a7, b2); fma2(acc[7][3], a7, b3);
        }
        __syncthreads();
    }

    #pragma unroll
    for (int i = 0; i < 8; i++) {
        int m = m0 + ty * 8 + i;
        if (m >= Meff) continue;
        int cidx = perm ? perm[m] : m;
        float* cr = C + (size_t)cidx * ldc;
        #pragma unroll
        for (int p = 0; p < 4; p++) {
            int nn = n0 + tx * 8 + p * 2;
            if (nn < N)     cr[nn]     = lo32(acc[i][p]) + (bias ? bias[nn] : 0.f);
            if (nn + 1 < N) cr[nn + 1] = hi32(acc[i][p]) + (bias ? bias[nn + 1] : 0.f);
        }
    }
}

// ------------------------- persistent decoder loop ---------------------------
__global__ void __launch_bounds__(256)
decoder_loop(const float* __restrict__ enc,
             const float* __restrict__ Wd, const float* __restrict__ Wf,
             const float* __restrict__ Whh,
             const float* __restrict__ b_dec, const float* __restrict__ b_fbeta,
             const float* __restrict__ w_full, const float* __restrict__ b_full,
             const float* __restrict__ Wih, const float* __restrict__ b_ih,
             const float* __restrict__ b_hh,
             const int* __restrict__ lang_idx, const int* __restrict__ lang_len,
             float* __restrict__ out_alpha)
{
    __shared__ __align__(16) char sm[24576];
    int tid = threadIdx.x, bid = blockIdx.x;
    int tx = tid & 15, ty = tid >> 4;
    unsigned round = 0;

    for (int t = 0; t < TQ; t++) {
        // ======================= P1 (pipelined) =======================
        if (bid < 126) {
            ull*   As2 = (ull*)sm;               // [16][128] ulls (16 KB)
            float* Bs  = (float*)(sm + 16384);   // [16][64]  (4 KB)
            int ks = bid % 3, nt = bid / 3;
            int k0 = ks * 176;
            int nkt = (ks < 2) ? 11 : 10;
            int br = tid >> 2, bk = (tid & 3) * 4;
            int n = nt * 64 + br;
            const float* Brow;
            if (n < 512)      Brow = Wd  + (size_t)n * DQ;
            else if (n < 640) Brow = Wf  + (size_t)(n - 512) * DQ;
            else              Brow = Whh + (size_t)(n - 640) * DQ;
            int lr = tid >> 1, lk = (tid & 1) * 8;

            ull acc[8][2];
            #pragma unroll
            for (int i = 0; i < 8; i++) { acc[i][0] = 0ull; acc[i][1] = 0ull; }

            float4 pa0 = __ldcg((const float4*)&g_h[lr * DQ + k0 + lk]);
            float4 pa1 = __ldcg((const float4*)&g_h[lr * DQ + k0 + lk + 4]);
            float4 pb  = __ldg((const float4*)&Brow[k0 + bk]);

            for (int kt = 0; kt < nkt; kt++) {
                As2[(lk + 0) * 128 + lr] = pk2(pa0.x, pa0.x);
                As2[(lk + 1) * 128 + lr] = pk2(pa0.y, pa0.y);
                As2[(lk + 2) * 128 + lr] = pk2(pa0.z, pa0.z);
                As2[(lk + 3) * 128 + lr] = pk2(pa0.w, pa0.w);
                As2[(lk + 4) * 128 + lr] = pk2(pa1.x, pa1.x);
                As2[(lk + 5) * 128 + lr] = pk2(pa1.y, pa1.y);
                As2[(lk + 6) * 128 + lr] = pk2(pa1.z, pa1.z);
                As2[(lk + 7) * 128 + lr] = pk2(pa1.w, pa1.w);
                Bs[(bk + 0) * 64 + br] = pb.x; Bs[(bk + 1) * 64 + br] = pb.y;
                Bs[(bk + 2) * 64 + br] = pb.z; Bs[(bk + 3) * 64 + br] = pb.w;
                __syncthreads();
                if (kt + 1 < nkt) {
                    int k = k0 + (kt + 1) * 16;
                    pa0 = __ldcg((const float4*)&g_h[lr * DQ + k + lk]);
                    pa1 = __ldcg((const float4*)&g_h[lr * DQ + k + lk + 4]);
                    pb  = __ldg((const float4*)&Brow[k + bk]);
                }
                #pragma unroll
                for (int kk = 0; kk < 16; kk++) {
                    const ull* ap = &As2[kk * 128 + ty * 8];
                    ull a0 = ap[0], a1 = ap[1], a2 = ap[2], a3 = ap[3];
                    ull a4 = ap[4], a5 = ap[5], a6 = ap[6], a7 = ap[7];
                    const ull* bp = (const ull*)&Bs[kk * 64 + tx * 4];
                    ull b0 = bp[0], b1 = bp[1];
                    fma2(acc[0][0], a0, b0); fma2(acc[0][1], a0, b1);
                    fma2(acc[1][0], a1, b0); fma2(acc[1][1], a1, b1);
                    fma2(acc[2][0], a2, b0); fma2(acc[2][1], a2, b1);
                    fma2(acc[3][0], a3, b0); fma2(acc[3][1], a3, b1);
                    fma2(acc[4][0], a4, b0); fma2(acc[4][1], a4, b1);
                    fma2(acc[5][0], a5, b0); fma2(acc[5][1], a5, b1);
                    fma2(acc[6][0], a6, b0); fma2(acc[6][1], a6, b1);
                    fma2(acc[7][0], a7, b0); fma2(acc[7][1], a7, b1);
                }
                __syncthreads();
            }
            float* Cp = g_Yp + (size_t)ks * BQ * YDIM + nt * 64;
            #pragma unroll
            for (int i = 0; i < 8; i++) {
                int m = ty * 8 + i;
                float4 o = make_float4(lo32(acc[i][0]), hi32(acc[i][0]),
                                       lo32(acc[i][1]), hi32(acc[i][1]));
                __stcg((float4*)&Cp[(size_t)m * YDIM + tx * 4], o);
            }
        }
        grid_bar((++round) * GRID_P);

        // ======================= P2 =======================
        if (bid < 128) {
            int b = bid;
            float* pool    = (float*)sm;
            float* att2_s  = pool;
            float* w_s     = pool + 512;
            float* att_s   = pool + 1024;
            float* red     = pool + 1152;
            float* alpha_s = pool + 1280;
            float* part    = pool + 1408;

            #pragma unroll
            for (int a = tid; a < AQ; a += 256) {
                float v = b_dec[a];
                #pragma unroll
                for (int s = 0; s < NSPLIT; s++)
                    v += __ldcg(&g_Yp[((size_t)s * BQ + b) * YDIM + a]);
                att2_s[a] = v;
                w_s[a] = w_full[a];
            }
            __syncthreads();

            int warp = tid >> 5, lane = tid & 31;
            #pragma unroll 2
            for (int k = warp; k < KQ; k += 8) {
                const float* a1 = g_att1 + ((size_t)b * KQ + k) * AQ;
                float s = 0.f;
                #pragma unroll
                for (int c = 0; c < 4; c++) {
                    int base = c * 128 + lane * 4;
                    float4 v = __ldg((const float4*)&a1[base]);
                    s += fmaxf(v.x + att2_s[base + 0], 0.f) * w_s[base + 0];
                    s += fmaxf(v.y + att2_s[base + 1], 0.f) * w_s[base + 1];
                    s += fmaxf(v.z + att2_s[base + 2], 0.f) * w_s[base + 2];
                    s += fmaxf(v.w + att2_s[base + 3], 0.f) * w_s[base + 3];
                }
                #pragma unroll
                for (int o = 16; o; o >>= 1) s += __shfl_down_sync(0xffffffffu, s, o);
                if (lane == 0) att_s[k] = s + b_full[0];
            }
            __syncthreads();

            if (tid < KQ)
                red[tid] = g_mask[b * KQ + tid] ? att_s[tid]
                                                : -__int_as_float(0x7f800000);
            __syncthreads();
            for (int s = 64; s > 0; s >>= 1) {
                if (tid < s) red[tid] = fmaxf(red[tid], red[tid + s]);
                __syncthreads();
            }
            float mx = red[0];
            if (isinf(mx)) mx = 0.f;
            __syncthreads();
            if (tid < KQ) {
                float e = g_mask[b * KQ + tid] ? expf(att_s[tid] - mx) : 0.f;
                alpha_s[tid] = e;
                red[tid] = e;
            }
            __syncthreads();
            for (int s = 64; s > 0; s >>= 1) {
                if (tid < s) red[tid] += red[tid + s];
                __syncthreads();
            }
            float dsum = red[0];
            float inv = (dsum > 0.f) ? 1.f / fmaxf(dsum, 1e-30f) : 0.f;
            __syncthreads();
            if (tid < KQ) alpha_s[tid] *= inv;
            __syncthreads();

            {
                int v = tid & (VDQ - 1), q = tid >> 7;
                const float* eb = enc + (size_t)b * KQ * VDQ;
                float s = 0.f;
                #pragma unroll 8
                for (int k = q * 64; k < q * 64 + 64; k++)
                    s += alpha_s[k] * __ldg(&eb[k * VDQ + v]);
                part[tid] = s;
            }
            __syncthreads();

            bool active = (t < lang_len[b]);
            if (tid < VDQ) {
                float aw = part[tid] + part[tid + 128];
                float gv = b_fbeta[tid];
                #pragma unroll
                for (int s = 0; s < NSPLIT; s++)
                    gv += __ldcg(&g_Yp[((size_t)s * BQ + b) * YDIM + 512 + tid]);
                __stcg(&g_awe[b * VDQ + tid], aw * sigf(gv));
                out_alpha[(size_t)b * TQ * KQ + (size_t)t * KQ + tid]
                    = active ? alpha_s[tid] : 0.f;
            }

            // fused Yhh partial reduction (same b)
            {
                int col = tid * 8;
                float4 s0 = make_float4(0.f, 0.f, 0.f, 0.f);
                float4 s1 = make_float4(0.f, 0.f, 0.f, 0.f);
                #pragma unroll
                for (int s = 0; s < NSPLIT; s++) {
                    const float* p = g_Yp + ((size_t)s * BQ + b) * YDIM + 640 + col;
                    float4 v0 = __ldcg((const float4*)p);
                    float4 v1 = __ldcg((const float4*)(p + 4));
                    s0.x += v0.x; s0.y += v0.y; s0.z += v0.z; s0.w += v0.w;
                    s1.x += v1.x; s1.y += v1.y; s1.z += v1.z; s1.w += v1.w;
                }
                __stcg((float4*)&g_Yhh[b * GN + col], s0);
                __stcg((float4*)&g_Yhh[b * GN + col + 4], s1);
            }
        }
        grid_bar((++round) * GRID_P);

        // ======================= P3 (pipelined) =======================
        if (bid < 128) {
            float* As  = (float*)sm;             // [16][64]
            float* Bs3 = (float*)(sm + 4096);    // [16][32]
            int m0 = (bid & 1) * 64;
            int jt = bid >> 1;
            int n0v = jt * 32;
            int am = tid >> 2, ak4 = (tid & 3) * 4;
            int vr = tid >> 3, kb = (tid & 7) * 2;
            int vcol = n0v + vr;
            int wr = (vcol & 3) * 512 + (vcol >> 2);
            const float* Brow = Wih + (size_t)wr * XDIM + EQ;

            int jx = tid & 7, my = tid >> 3;
            ull acc[2][2] = {{0ull, 0ull}, {0ull, 0ull}};

            float4 pa = __ldcg((const float4*)&g_awe[(m0 + am) * VDQ + ak4]);
            float2 pb = *(const float2*)&Brow[kb];

            for (int kt = 0; kt < 8; kt++) {
                As[(ak4 + 0) * 64 + am] = pa.x; As[(ak4 + 1) * 64 + am] = pa.y;
                As[(ak4 + 2) * 64 + am] = pa.z; As[(ak4 + 3) * 64 + am] = pa.w;
                Bs3[(kb + 0) * 32 + vr] = pb.x;
                Bs3[(kb + 1) * 32 + vr] = pb.y;
                __syncthreads();
                if (kt + 1 < 8) {
                    int k = (kt + 1) * 16;
                    pa = __ldcg((const float4*)&g_awe[(m0 + am) * VDQ + k + ak4]);
                    pb = *(const float2*)&Brow[k + kb];
                }
                #pragma unroll
                for (int kk = 0; kk < 16; kk++) {
                    float2 a2 = *(const float2*)&As[kk * 64 + my * 2];
                    const ull* bp = (const ull*)&Bs3[kk * 32 + jx * 4];
                    ull b01 = bp[0], b23 = bp[1];
                    ull pa0 = pk2(a2.x, a2.x), pa1 = pk2(a2.y, a2.y);
                    fma2(acc[0][0], pa0, b01); fma2(acc[0][1], pa0, b23);
                    fma2(acc[1][0], pa1, b01); fma2(acc[1][1], pa1, b23);
                }
                __syncthreads();
            }

            int j = jt * 8 + jx;
            float bi_i = b_ih[j]        + b_hh[j];
            float bi_f = b_ih[512 + j]  + b_hh[512 + j];
            float bi_g = b_ih[1024 + j] + b_hh[1024 + j];
            float bi_o = b_ih[1536 + j] + b_hh[1536 + j];
            #pragma unroll
            for (int i = 0; i < 2; i++) {
                int b = m0 + my * 2 + i;
                const float* Gv = (t == 0) ? g_Ginit
                    : g_Gv + (size_t)__ldg(&lang_idx[b * TQ + (t - 1)]) * GN;
                float gi = lo32(acc[i][0]) + Gv[j]        + g_Gref[b * GN + j]        + __ldcg(&g_Yhh[b * GN + j])        + bi_i;
                float gf = hi32(acc[i][0]) + Gv[512 + j]  + g_Gref[b * GN + 512 + j]  + __ldcg(&g_Yhh[b * GN + 512 + j])  + bi_f;
                float gg = lo32(acc[i][1]) + Gv[1024 + j] + g_Gref[b * GN + 1024 + j] + __ldcg(&g_Yhh[b * GN + 1024 + j]) + bi_g;
                float go = hi32(acc[i][1]) + Gv[1536 + j] + g_Gref[b * GN + 1536 + j] + __ldcg(&g_Yhh[b * GN + 1536 + j]) + bi_o;
                float c_old = __ldcg(&g_c[b * DQ + j]);
                float cn = sigf(gf) * c_old + sigf(gi) * tanhf(gg);
                float hn = sigf(go) * tanhf(cn);
                bool act = t < lang_len[b];
                float h_prev = __ldcg(&g_h[b * DQ + j]);
                float h_out = act ? hn : h_prev;
                if (act) {
                    __stcg(&g_c[b * DQ + j], cn);
                    __stcg(&g_h[b * DQ + j], hn);
                }
                g_hstore[((size_t)t * BQ + b) * DQ + j] = h_out;
            }
        }
        if (t != TQ - 1) grid_bar((++round) * GRID_P);
    }

    // done protocol (reset counters for next graph replay)
    __syncthreads();
    __threadfence();
    if (tid == 0) {
        asm volatile("red.release.gpu.global.add.u32 [%0], %1;"
                     :: "l"(&g_done), "r"(1u) : "memory");
        if (bid == 0) {
            unsigned v;
            do {
                asm volatile("ld.acquire.gpu.global.u32 %0, [%1];"
                             : "=r"(v) : "l"(&g_done) : "memory");
            } while (v < (unsigned)GRID_P);
            asm volatile("st.global.cg.u32 [%0], %1;" :: "l"(&g_bar), "r"(0u) : "memory");
            __threadfence();
            asm volatile("st.release.gpu.global.u32 [%0], %1;"
                         :: "l"(&g_done), "r"(0u) : "memory");
        }
    }
}

// ---------- final: mask + transpose [T,B,V] -> [B,V,T] ------------------------
__global__ void transpose_preds(const int* __restrict__ lang_len,
                                float* __restrict__ out)
{
    __shared__ float tile[32][33];
    int b = blockIdx.x;
    int v0 = blockIdx.y * 32;
    int tx = threadIdx.x, ty = threadIdx.y;
    float s = 0.f;
    if (ty < lang_len[b])
        s = g_predsT[(size_t)ty * BQ * VQ + (size_t)b * VQ + v0 + tx];
    tile[ty][tx] = s;
    __syncthreads();
    out[(size_t)b * VQ * TQ + (size_t)(v0 + ty) * TQ + tx] = tile[tx][ty];
}

// ------------------------- launch ---------------------------------------------
extern "C" void kernel_launch(void* const* d_in, const int* in_sizes, int n_in,
                              void* d_out, int out_size)
{
    const float* enc       = (const float*)d_in[0];
    const float* ref_obj   = (const float*)d_in[1];
    const float* obj_sc    = (const float*)d_in[2];
    const float* center    = (const float*)d_in[3];
    const float* xyz       = (const float*)d_in[4];
    const int*   lang_idx  = (const int*)d_in[5];
    const int*   lang_len  = (const int*)d_in[6];
    const float* emb_tab   = (const float*)d_in[7];
    const float* init_emb  = (const float*)d_in[8];
    const float* W_enc_att = (const float*)d_in[9];
    const float* b_enc_att = (const float*)d_in[10];
    const float* W_dec_att = (const float*)d_in[11];
    const float* b_dec_att = (const float*)d_in[12];
    const float* w_full    = (const float*)d_in[13];
    const float* b_full    = (const float*)d_in[14];
    const float* W_ih      = (const float*)d_in[15];
    const float* b_ih      = (const float*)d_in[16];
    const float* W_hh      = (const float*)d_in[17];
    const float* b_hh      = (const float*)d_in[18];
    const float* W_init_h  = (const float*)d_in[19];
    const float* b_init_h  = (const float*)d_in[20];
    const float* W_init_c  = (const float*)d_in[21];
    const float* b_init_c  = (const float*)d_in[22];
    const float* W_fbeta   = (const float*)d_in[23];
    const float* b_fbeta   = (const float*)d_in[24];
    const float* W_fc      = (const float*)d_in[25];
    const float* b_fc      = (const float*)d_in[26];

    float* out       = (float*)d_out;
    float* out_alpha = out + (size_t)BQ * VQ * TQ;
    float* out_mask  = out_alpha + (size_t)BQ * TQ * KQ;

    float *p_att1, *p_Gv, *p_Gref, *p_hstore, *p_predsT;
    int *p_perm, *p_nact;
    cudaGetSymbolAddress((void**)&p_att1,   g_att1);
    cudaGetSymbolAddress((void**)&p_Gv,     g_Gv);
    cudaGetSymbolAddress((void**)&p_Gref,   g_Gref);
    cudaGetSymbolAddress((void**)&p_hstore, g_hstore);
    cudaGetSymbolAddress((void**)&p_predsT, g_predsT);
    cudaGetSymbolAddress((void**)&p_perm,   g_perm);
    cudaGetSymbolAddress((void**)&p_nact,   g_nact);

    fused_pre<<<264, 256>>>(obj_sc, center, xyz, enc, ref_obj, init_emb,
                            W_ih, out_mask);
    init_hc<<<dim3(16, 4), 256>>>(W_init_h, b_init_h, W_init_c, b_init_c);
    gemm128<<<dim3(16, 1), 256>>>(ref_obj, ODQ, W_ih + EQ + VDQ, XDIM, nullptr,
                                  p_Gref, GN, BQ, GN, ODQ, nullptr, nullptr);
    gemm128<<<dim3(4, 128), 256>>>(enc, VDQ, W_enc_att, VDQ, b_enc_att,
                                   p_att1, AQ, BQ * KQ, AQ, VDQ, nullptr, nullptr);
    gemm128<<<dim3(16, 32), 256>>>(emb_tab, EQ, W_ih, XDIM, nullptr,
                                   p_Gv, GN, VQ, GN, EQ, nullptr, nullptr);
    decoder_loop<<<GRID_P, 256>>>(enc, W_dec_att, W_fbeta, W_hh,
                                  b_dec_att, b_fbeta, w_full, b_full,
                                  W_ih, b_ih, b_hh, lang_idx, lang_len,
                                  out_alpha);
    build_perm<<<1, 256>>>(lang_len);
    gemm128<<<dim3(32, 32), 256>>>(p_hstore, DQ, W_fc, DQ, b_fc,
                                   p_predsT, VQ, TQ * BQ, VQ, DQ, p_perm, p_nact);
    transpose_preds<<<dim3(BQ, VQ / 32), dim3(32, 32)>>>(lang_len, out);
}

// round 13
// speedup vs baseline: 1.7843x; 1.0935x over previous
#include <cuda_runtime.h>
#include <math.h>
#include <stdint.h>

#define BQ 128
#define KQ 128
#define VDQ 128
#define ODQ 256
#define EQ 300
#define AQ 512
#define DQ 512
#define VQ 4000
#define TQ 32
#define XDIM 684
#define YDIM 2688    // 512 dec | 128 fbeta | 2048 hh
#define GN 2048
#define GRID_P 128
#define NSPLIT 3

// ------------------------- scratch (device globals) -------------------------
__device__ float g_att1[(size_t)BQ * KQ * AQ];           // 32 MB
__device__ float g_Yp[(size_t)NSPLIT * BQ * YDIM];
__device__ float g_Yhh[BQ * GN];
__device__ float g_h[BQ * DQ];
__device__ float g_c[BQ * DQ];
__device__ float g_awe[BQ * VDQ];
__device__ float g_init[BQ * (VDQ + ODQ)];
__device__ float g_Gv[(size_t)VQ * GN];                  // 32.8 MB
__device__ float g_Gref[BQ * GN];
__device__ float g_Ginit[GN];
__device__ float g_hstore[(size_t)TQ * BQ * DQ];
__device__ float g_predsT[(size_t)TQ * BQ * VQ];         // 64 MB
__device__ unsigned char g_mask[BQ * KQ];
__device__ int g_perm[TQ * BQ];
__device__ int g_nact;
__device__ int g_border[BQ];     // batches sorted by lang_len desc
__device__ int g_ncnt[TQ + 1];   // ncnt[t] = #{b : lang_len[b] > t}
__device__ unsigned g_bar = 0;
__device__ unsigned g_done = 0;

typedef unsigned long long ull;
__device__ __forceinline__ ull pk2(float x, float y) {
    ull r; asm("mov.b64 %0,{%1,%2};" : "=l"(r) : "f"(x), "f"(y)); return r;
}
__device__ __forceinline__ void fma2(ull& d, ull a, ull b) {
    asm("fma.rn.f32x2 %0,%1,%2,%0;" : "+l"(d) : "l"(a), "l"(b));
}
__device__ __forceinline__ float lo32(ull v) { return __uint_as_float((unsigned)v); }
__device__ __forceinline__ float hi32(ull v) { return __uint_as_float((unsigned)(v >> 32)); }
__device__ __forceinline__ float sigf(float x) { return 1.f / (1.f + expf(-x)); }

// flat grid barrier (round-9 proven): release-RED arrive + acquire spin
__device__ __forceinline__ void grid_bar(unsigned target)
{
    __syncthreads();
    if (threadIdx.x == 0) {
        asm volatile("red.release.gpu.global.add.u32 [%0], %1;"
                     :: "l"(&g_bar), "r"(1u) : "memory");
        unsigned v;
        do {
            asm volatile("ld.acquire.gpu.global.u32 %0, [%1];"
                         : "=r"(v) : "l"(&g_bar) : "memory");
        } while (v < target);
    }
    __syncthreads();
}

__device__ __forceinline__ float4 ld4g_ro(const float* base, int k, int limit) {
    if (k + 4 <= limit) return __ldg((const float4*)(base + k));
    float4 v = make_float4(0.f, 0.f, 0.f, 0.f);
    if (k + 0 < limit) v.x = __ldg(base + k + 0);
    if (k + 1 < limit) v.y = __ldg(base + k + 1);
    if (k + 2 < limit) v.z = __ldg(base + k + 2);
    if (k + 3 < limit) v.w = __ldg(base + k + 3);
    return v;
}

// ---------------- fused precompute: mask | init | Ginit | sort ---------------
__global__ void fused_pre(const float* __restrict__ obj,
                          const float* __restrict__ center,
                          const float* __restrict__ xyz,
                          const float* __restrict__ enc,
                          const float* __restrict__ ref_obj,
                          const float* __restrict__ init_emb,
                          const float* __restrict__ Wih,
                          const int* __restrict__ lang_len,
                          float* __restrict__ out_mask)
{
    int bid = blockIdx.x, tid = threadIdx.x;
    if (bid < 128) {
        __shared__ float ds[KQ];
        __shared__ float dk[KQ];
        int b = bid, k = tid;
        const float INF = __int_as_float(0x7f800000);
        float d = INF; bool om = false;
        if (k < KQ) {
            float s0 = obj[(b * KQ + k) * 2];
            float s1 = obj[(b * KQ + k) * 2 + 1];
            om = (1.f / (1.f + expf(s0 - s1))) > 0.75f;
            float dx = center[b * 3 + 0] - xyz[(b * KQ + k) * 3 + 0];
            float dy = center[b * 3 + 1] - xyz[(b * KQ + k) * 3 + 1];
            float dz = center[b * 3 + 2] - xyz[(b * KQ + k) * 3 + 2];
            float dist = sqrtf(dx * dx + dy * dy + dz * dz);
            d = om ? dist : INF;
            ds[k] = d; dk[k] = d;
        }
        __syncthreads();
        for (int sz = 2; sz <= KQ; sz <<= 1) {
            for (int j = sz >> 1; j > 0; j >>= 1) {
                if (k < KQ) {
                    int ixj = k ^ j;
                    if (ixj > k) {
                        bool up = ((k & sz) == 0);
                        float a = ds[k], bb = ds[ixj];
                        if ((a > bb) == up) { ds[k] = bb; ds[ixj] = a; }
                    }
                }
                __syncthreads();
            }
        }
        if (k < KQ) {
            float maxd = ds[15];
            bool msk = om && (dk[k] <= maxd);
            g_mask[b * KQ + k] = msk ? 1 : 0;
            out_mask[b * KQ + k] = msk ? 1.f : 0.f;
        }
    } else if (bid < 256) {
        int b = bid - 128;
        if (tid < VDQ) {
            float s = 0.f;
            const float* eb = enc + (size_t)b * KQ * VDQ;
            #pragma unroll 4
            for (int k = 0; k < KQ; k++) s += eb[k * VDQ + tid];
            g_init[b * (VDQ + ODQ) + tid] = s * (1.f / (float)KQ);
        }
        g_init[b * (VDQ + ODQ) + VDQ + tid] = ref_obj[b * ODQ + tid];
    } else if (bid < 264) {
        int r = (bid - 256) * 256 + tid;
        const float* wr = Wih + (size_t)r * XDIM;
        float s = 0.f;
        #pragma unroll 4
        for (int k = 0; k < EQ; k++) s += init_emb[k] * wr[k];
        g_Ginit[r] = s;
    } else {
        // counting sort of batches by lang_len, descending (stable)
        if (tid == 0) {
            int cnt[33];
            for (int i = 0; i < 33; i++) cnt[i] = 0;
            for (int b = 0; b < BQ; b++) cnt[lang_len[b]]++;
            int off[34];
            off[33] = 0; off[32] = 0;
            for (int L = 31; L >= 0; L--) off[L] = off[L + 1] + cnt[L + 1];
            for (int t = 0; t <= TQ; t++) g_ncnt[t] = off[t];
            int pos[33];
            for (int i = 0; i < 33; i++) pos[i] = off[i];
            for (int b = 0; b < BQ; b++) {
                int L = lang_len[b];
                g_border[pos[L]++] = b;
            }
        }
    }
}

// ---------------- build active-row permutation for fc ------------------------
__global__ void build_perm(const int* __restrict__ lang_len)
{
    __shared__ unsigned cnt;
    int tid = threadIdx.x;
    if (tid == 0) cnt = 0;
    __syncthreads();
    for (int r = tid; r < TQ * BQ; r += 256) {
        int t = r >> 7, b = r & 127;
        if (t < lang_len[b]) {
            unsigned p = atomicAdd(&cnt, 1u);
            g_perm[p] = r;
        }
    }
    __syncthreads();
    if (tid == 0) g_nact = (int)cnt;
}

// ------------------------- init h0/c0 fused GEMM -----------------------------
__global__ void init_hc(const float* __restrict__ Wh, const float* __restrict__ bh,
                        const float* __restrict__ Wc, const float* __restrict__ bc)
{
    const int K = VDQ + ODQ;
    __shared__ float As[16 * 32];
    __shared__ float Bs[16 * 64];
    int tid = threadIdx.x;
    int m0 = blockIdx.y * 32;
    int n0 = blockIdx.x * 64;
    const float* Bp; const float* bias; float* out; int col;
    if (n0 < 512) { Bp = Wh; bias = bh; out = g_h; col = n0; }
    else          { Bp = Wc; bias = bc; out = g_c; col = n0 - 512; }

    int tx = tid & 15, ty = tid >> 4;
    ull acc[2][2] = {{0ull, 0ull}, {0ull, 0ull}};

    for (int k0 = 0; k0 < K; k0 += 16) {
        if (tid < 128) {
            int m = tid >> 2, kq = (tid & 3) * 4;
            float4 v = *(const float4*)&g_init[(m0 + m) * K + k0 + kq];
            As[(kq + 0) * 32 + m] = v.x; As[(kq + 1) * 32 + m] = v.y;
            As[(kq + 2) * 32 + m] = v.z; As[(kq + 3) * 32 + m] = v.w;
        }
        {
            int n = tid >> 2, kq = (tid & 3) * 4;
            float4 v = *(const float4*)&Bp[(size_t)(col + n) * K + k0 + kq];
            Bs[(kq + 0) * 64 + n] = v.x; Bs[(kq + 1) * 64 + n] = v.y;
            Bs[(kq + 2) * 64 + n] = v.z; Bs[(kq + 3) * 64 + n] = v.w;
        }
        __syncthreads();
        #pragma unroll
        for (int kk = 0; kk < 16; kk++) {
            float2 a = *(const float2*)&As[kk * 32 + ty * 2];
            ull a0 = pk2(a.x, a.x), a1 = pk2(a.y, a.y);
            const ull* bp = (const ull*)&Bs[kk * 64 + tx * 4];
            ull b01 = bp[0], b23 = bp[1];
            fma2(acc[0][0], a0, b01); fma2(acc[0][1], a0, b23);
            fma2(acc[1][0], a1, b01); fma2(acc[1][1], a1, b23);
        }
        __syncthreads();
    }
    #pragma unroll
    for (int i = 0; i < 2; i++) {
        int m = m0 + ty * 2 + i;
        int nb = col + tx * 4;
        float* cr = out + m * DQ + nb;
        cr[0] = lo32(acc[i][0]) + bias[nb + 0];
        cr[1] = hi32(acc[i][0]) + bias[nb + 1];
        cr[2] = lo32(acc[i][1]) + bias[nb + 2];
        cr[3] = hi32(acc[i][1]) + bias[nb + 3];
    }
}

// ------------- gemm128: C[M,N] = A[M,:K] @ B[N,:K]^T (+bias) -----------------
__global__ void __launch_bounds__(256)
gemm128(const float* __restrict__ A, int lda,
        const float* __restrict__ B, int ldb,
        const float* __restrict__ bias, float* __restrict__ C, int ldc,
        int M, int N, int K,
        const int* __restrict__ perm, const int* __restrict__ nact_p)
{
    __shared__ ull As2[16 * 128];
    __shared__ float Bs[16 * 128];
    int tid = threadIdx.x;
    int m0 = blockIdx.y * 128, n0 = blockIdx.x * 128;
    int Meff = M;
    if (nact_p) { Meff = *nact_p; if (m0 >= Meff) return; }

    int lr = tid >> 1, lk = (tid & 1) * 8;
    int arow = m0 + lr; if (arow >= Meff) arow = Meff - 1;
    int aidx = perm ? perm[arow] : arow;
    int brow = n0 + lr; if (brow >= N) brow = N - 1;
    const float* Ap = A + (size_t)aidx * lda;
    const float* Bp = B + (size_t)brow * ldb;
    int tx = tid & 15, ty = tid >> 4;

    ull acc[8][4];
    #pragma unroll
    for (int i = 0; i < 8; i++)
        #pragma unroll
        for (int p = 0; p < 4; p++) acc[i][p] = 0ull;

    float4 ra0 = ld4g_ro(Ap, lk, K),     ra1 = ld4g_ro(Ap, lk + 4, K);
    float4 rb0 = ld4g_ro(Bp, lk, K),     rb1 = ld4g_ro(Bp, lk + 4, K);

    for (int k0 = 0; k0 < K; k0 += 16) {
        As2[(lk + 0) * 128 + lr] = pk2(ra0.x, ra0.x);
        As2[(lk + 1) * 128 + lr] = pk2(ra0.y, ra0.y);
        As2[(lk + 2) * 128 + lr] = pk2(ra0.z, ra0.z);
        As2[(lk + 3) * 128 + lr] = pk2(ra0.w, ra0.w);
        As2[(lk + 4) * 128 + lr] = pk2(ra1.x, ra1.x);
        As2[(lk + 5) * 128 + lr] = pk2(ra1.y, ra1.y);
        As2[(lk + 6) * 128 + lr] = pk2(ra1.z, ra1.z);
        As2[(lk + 7) * 128 + lr] = pk2(ra1.w, ra1.w);
        Bs[(lk + 0) * 128 + lr] = rb0.x; Bs[(lk + 1) * 128 + lr] = rb0.y;
        Bs[(lk + 2) * 128 + lr] = rb0.z; Bs[(lk + 3) * 128 + lr] = rb0.w;
        Bs[(lk + 4) * 128 + lr] = rb1.x; Bs[(lk + 5) * 128 + lr] = rb1.y;
        Bs[(lk + 6) * 128 + lr] = rb1.z; Bs[(lk + 7) * 128 + lr] = rb1.w;
        __syncthreads();
        int kn = k0 + 16;
        if (kn < K) {
            ra0 = ld4g_ro(Ap, kn + lk, K); ra1 = ld4g_ro(Ap, kn + lk + 4, K);
            rb0 = ld4g_ro(Bp, kn + lk, K); rb1 = ld4g_ro(Bp, kn + lk + 4, K);
        }
        #pragma unroll
        for (int kk = 0; kk < 16; kk++) {
            const ull* ap = &As2[kk * 128 + ty * 8];
            ull a0 = ap[0], a1 = ap[1], a2 = ap[2], a3 = ap[3];
            ull a4 = ap[4], a5 = ap[5], a6 = ap[6], a7 = ap[7];
            const ull* bp = (const ull*)&Bs[kk * 128 + tx * 8];
            ull b0 = bp[0], b1 = bp[1], b2 = bp[2], b3 = bp[3];
            fma2(acc[0][0], a0, b0); fma2(acc[0][1], a0, b1); fma2(acc[0][2], a0, b2); fma2(acc[0][3], a0, b3);
            fma2(acc[1][0], a1, b0); fma2(acc[1][1], a1, b1); fma2(acc[1][2], a1, b2); fma2(acc[1][3], a1, b3);
            fma2(acc[2][0], a2, b0); fma2(acc[2][1], a2, b1); fma2(acc[2][2], a2, b2); fma2(acc[2][3], a2, b3);
            fma2(acc[3][0], a3, b0); fma2(acc[3][1], a3, b1); fma2(acc[3][2], a3, b2); fma2(acc[3][3], a3, b3);
            fma2(acc[4][0], a4, b0); fma2(acc[4][1], a4, b1); fma2(acc[4][2], a4, b2); fma2(acc[4][3], a4, b3);
            fma2(acc[5][0], a5, b0); fma2(acc[5][1], a5, b1); fma2(acc[5][2], a5, b2); fma2(acc[5][3], a5, b3);
            fma2(acc[6][0], a6, b0); fma2(acc[6][1], a6, b1); fma2(acc[6][2], a6, b2); fma2(acc[6][3], a6, b3);
            fma2(acc[7][0], a7, b0); fma2(acc[7][1], a7, b1); fma2(acc[7][2], a7, b2); fma2(acc[7][3], a7, b3);
        }
        __syncthreads();
    }

    #pragma unroll
    for (int i = 0; i < 8; i++) {
        int m = m0 + ty * 8 + i;
        if (m >= Meff) continue;
        int cidx = perm ? perm[m] : m;
        float* cr = C + (size_t)cidx * ldc;
        #pragma unroll
        for (int p = 0; p < 4; p++) {
            int nn = n0 + tx * 8 + p * 2;
            if (nn < N)     cr[nn]     = lo32(acc[i][p]) + (bias ? bias[nn] : 0.f);
            if (nn + 1 < N) cr[nn + 1] = hi32(acc[i][p]) + (bias ? bias[nn + 1] : 0.f);
        }
    }
}

// ------------------------- persistent decoder loop ---------------------------
__global__ void __launch_bounds__(256)
decoder_loop(const float* __restrict__ enc,
             const float* __restrict__ Wd, const float* __restrict__ Wf,
             const float* __restrict__ Whh,
             const float* __restrict__ b_dec, const float* __restrict__ b_fbeta,
             const float* __restrict__ w_full, const float* __restrict__ b_full,
             const float* __restrict__ Wih, const float* __restrict__ b_ih,
             const float* __restrict__ b_hh,
             const int* __restrict__ lang_idx, const int* __restrict__ lang_len,
             float* __restrict__ out_alpha)
{
    __shared__ __align__(16) char sm[24576];
    int tid = threadIdx.x, bid = blockIdx.x;
    int tx = tid & 15, ty = tid >> 4;
    unsigned round = 0;

    for (int t = 0; t < TQ; t++) {
        // ======================= P1: Y rows for batches whose h changed =======
        int navail = (t == 0) ? BQ : __ldg(&g_ncnt[t - 1]);
        if (bid < 126 && navail > 0) {
            int ks = bid % 3, nt = bid / 3;
            int k0 = ks * 176;
            int nkt = (ks < 2) ? 11 : 10;
            int br = tid >> 2, bk = (tid & 3) * 4;
            int n = nt * 64 + br;
            const float* Brow;
            if (n < 512)      Brow = Wd  + (size_t)n * DQ;
            else if (n < 640) Brow = Wf  + (size_t)(n - 512) * DQ;
            else              Brow = Whh + (size_t)(n - 640) * DQ;
            float* Cp = g_Yp + (size_t)ks * BQ * YDIM + nt * 64;

            if (navail > 64) {
                // ---- 128-row gather path ----
                ull*   As2 = (ull*)sm;               // [16][128]
                float* Bs  = (float*)(sm + 16384);   // [16][64]
                int lr = tid >> 1, lk = (tid & 1) * 8;
                int ai = lr; if (ai >= navail) ai = navail - 1;
                const float* Ah = g_h + (size_t)__ldg(&g_border[ai]) * DQ;

                ull acc[8][2];
                #pragma unroll
                for (int i = 0; i < 8; i++) { acc[i][0] = 0ull; acc[i][1] = 0ull; }

                float4 pa0 = __ldcg((const float4*)&Ah[k0 + lk]);
                float4 pa1 = __ldcg((const float4*)&Ah[k0 + lk + 4]);
                float4 pb  = __ldg((const float4*)&Brow[k0 + bk]);

                for (int kt = 0; kt < nkt; kt++) {
                    As2[(lk + 0) * 128 + lr] = pk2(pa0.x, pa0.x);
                    As2[(lk + 1) * 128 + lr] = pk2(pa0.y, pa0.y);
                    As2[(lk + 2) * 128 + lr] = pk2(pa0.z, pa0.z);
                    As2[(lk + 3) * 128 + lr] = pk2(pa0.w, pa0.w);
                    As2[(lk + 4) * 128 + lr] = pk2(pa1.x, pa1.x);
                    As2[(lk + 5) * 128 + lr] = pk2(pa1.y, pa1.y);
                    As2[(lk + 6) * 128 + lr] = pk2(pa1.z, pa1.z);
                    As2[(lk + 7) * 128 + lr] = pk2(pa1.w, pa1.w);
                    Bs[(bk + 0) * 64 + br] = pb.x; Bs[(bk + 1) * 64 + br] = pb.y;
                    Bs[(bk + 2) * 64 + br] = pb.z; Bs[(bk + 3) * 64 + br] = pb.w;
                    __syncthreads();
                    if (kt + 1 < nkt) {
                        int k = k0 + (kt + 1) * 16;
                        pa0 = __ldcg((const float4*)&Ah[k + lk]);
                        pa1 = __ldcg((const float4*)&Ah[k + lk + 4]);
                        pb  = __ldg((const float4*)&Brow[k + bk]);
                    }
                    #pragma unroll
                    for (int kk = 0; kk < 16; kk++) {
                        const ull* ap = &As2[kk * 128 + ty * 8];
                        ull a0 = ap[0], a1 = ap[1], a2 = ap[2], a3 = ap[3];
                        ull a4 = ap[4], a5 = ap[5], a6 = ap[6], a7 = ap[7];
                        const ull* bp = (const ull*)&Bs[kk * 64 + tx * 4];
                        ull b0 = bp[0], b1 = bp[1];
                        fma2(acc[0][0], a0, b0); fma2(acc[0][1], a0, b1);
                        fma2(acc[1][0], a1, b0); fma2(acc[1][1], a1, b1);
                        fma2(acc[2][0], a2, b0); fma2(acc[2][1], a2, b1);
                        fma2(acc[3][0], a3, b0); fma2(acc[3][1], a3, b1);
                        fma2(acc[4][0], a4, b0); fma2(acc[4][1], a4, b1);
                        fma2(acc[5][0], a5, b0); fma2(acc[5][1], a5, b1);
                        fma2(acc[6][0], a6, b0); fma2(acc[6][1], a6, b1);
                        fma2(acc[7][0], a7, b0); fma2(acc[7][1], a7, b1);
                    }
                    __syncthreads();
                }
                #pragma unroll
                for (int i = 0; i < 8; i++) {
                    int m = ty * 8 + i;
                    if (m >= navail) continue;      // pure stores; skip dups
                    int ob = __ldg(&g_border[m]);
                    float4 o = make_float4(lo32(acc[i][0]), hi32(acc[i][0]),
                                           lo32(acc[i][1]), hi32(acc[i][1]));
                    __stcg((float4*)&Cp[(size_t)ob * YDIM + tx * 4], o);
                }
            } else {
                // ---- 64-row gather path (half work) ----
                ull*   As2 = (ull*)sm;               // [16][64]
                float* Bs  = (float*)(sm + 8192);    // [16][64]
                int lr = tid >> 1, lk = (tid & 1) * 8;
                const float* Ah = nullptr;
                if (tid < 128) {
                    int ai = lr; if (ai >= navail) ai = navail - 1;
                    Ah = g_h + (size_t)__ldg(&g_border[ai]) * DQ;
                }

                ull acc[4][2];
                #pragma unroll
                for (int i = 0; i < 4; i++) { acc[i][0] = 0ull; acc[i][1] = 0ull; }

                float4 pa0, pa1, pb;
                if (tid < 128) {
                    pa0 = __ldcg((const float4*)&Ah[k0 + lk]);
                    pa1 = __ldcg((const float4*)&Ah[k0 + lk + 4]);
                }
                pb = __ldg((const float4*)&Brow[k0 + bk]);

                for (int kt = 0; kt < nkt; kt++) {
                    if (tid < 128) {
                        As2[(lk + 0) * 64 + lr] = pk2(pa0.x, pa0.x);
                        As2[(lk + 1) * 64 + lr] = pk2(pa0.y, pa0.y);
                        As2[(lk + 2) * 64 + lr] = pk2(pa0.z, pa0.z);
                        As2[(lk + 3) * 64 + lr] = pk2(pa0.w, pa0.w);
                        As2[(lk + 4) * 64 + lr] = pk2(pa1.x, pa1.x);
                        As2[(lk + 5) * 64 + lr] = pk2(pa1.y, pa1.y);
                        As2[(lk + 6) * 64 + lr] = pk2(pa1.z, pa1.z);
                        As2[(lk + 7) * 64 + lr] = pk2(pa1.w, pa1.w);
                    }
                    Bs[(bk + 0) * 64 + br] = pb.x; Bs[(bk + 1) * 64 + br] = pb.y;
                    Bs[(bk + 2) * 64 + br] = pb.z; Bs[(bk + 3) * 64 + br] = pb.w;
                    __syncthreads();
                    if (kt + 1 < nkt) {
                        int k = k0 + (kt + 1) * 16;
                        if (tid < 128) {
                            pa0 = __ldcg((const float4*)&Ah[k + lk]);
                            pa1 = __ldcg((const float4*)&Ah[k + lk + 4]);
                        }
                        pb = __ldg((const float4*)&Brow[k + bk]);
                    }
                    #pragma unroll
                    for (int kk = 0; kk < 16; kk++) {
                        const ull* ap = &As2[kk * 64 + ty * 4];
                        ull a0 = ap[0], a1 = ap[1], a2 = ap[2], a3 = ap[3];
                        const ull* bp = (const ull*)&Bs[kk * 64 + tx * 4];
                        ull b0 = bp[0], b1 = bp[1];
                        fma2(acc[0][0], a0, b0); fma2(acc[0][1], a0, b1);
                        fma2(acc[1][0], a1, b0); fma2(acc[1][1], a1, b1);
                        fma2(acc[2][0], a2, b0); fma2(acc[2][1], a2, b1);
                        fma2(acc[3][0], a3, b0); fma2(acc[3][1], a3, b1);
                    }
                    __syncthreads();
                }
                #pragma unroll
                for (int i = 0; i < 4; i++) {
                    int m = ty * 4 + i;
                    if (m >= navail) continue;      // pure stores; skip dups
                    int ob = __ldg(&g_border[m]);
                    float4 o = make_float4(lo32(acc[i][0]), hi32(acc[i][0]),
                                           lo32(acc[i][1]), hi32(acc[i][1]));
                    __stcg((float4*)&Cp[(size_t)ob * YDIM + tx * 4], o);
                }
            }
        }
        grid_bar((++round) * GRID_P);

        // ======================= P2: attention (all 128 batches) =============
        {
            int b = bid;
            float* pool    = (float*)sm;
            float* att2_s  = pool;
            float* w_s     = pool + 512;
            float* att_s   = pool + 1024;
            float* red     = pool + 1152;
            float* alpha_s = pool + 1280;
            float* part    = pool + 1408;

            #pragma unroll
            for (int a = tid; a < AQ; a += 256) {
                float v = b_dec[a];
                #pragma unroll
                for (int s = 0; s < NSPLIT; s++)
                    v += __ldcg(&g_Yp[((size_t)s * BQ + b) * YDIM + a]);
                att2_s[a] = v;
                w_s[a] = w_full[a];
            }
            __syncthreads();

            int warp = tid >> 5, lane = tid & 31;
            #pragma unroll 2
            for (int k = warp; k < KQ; k += 8) {
                const float* a1 = g_att1 + ((size_t)b * KQ + k) * AQ;
                float s = 0.f;
                #pragma unroll
                for (int c = 0; c < 4; c++) {
                    int base = c * 128 + lane * 4;
                    float4 v = __ldg((const float4*)&a1[base]);
                    s += fmaxf(v.x + att2_s[base + 0], 0.f) * w_s[base + 0];
                    s += fmaxf(v.y + att2_s[base + 1], 0.f) * w_s[base + 1];
                    s += fmaxf(v.z + att2_s[base + 2], 0.f) * w_s[base + 2];
                    s += fmaxf(v.w + att2_s[base + 3], 0.f) * w_s[base + 3];
                }
                #pragma unroll
                for (int o = 16; o; o >>= 1) s += __shfl_down_sync(0xffffffffu, s, o);
                if (lane == 0) att_s[k] = s + b_full[0];
            }
            __syncthreads();

            if (tid < KQ)
                red[tid] = g_mask[b * KQ + tid] ? att_s[tid]
                                                : -__int_as_float(0x7f800000);
            __syncthreads();
            for (int s = 64; s > 0; s >>= 1) {
                if (tid < s) red[tid] = fmaxf(red[tid], red[tid + s]);
                __syncthreads();
            }
            float mx = red[0];
            if (isinf(mx)) mx = 0.f;
            __syncthreads();
            if (tid < KQ) {
                float e = g_mask[b * KQ + tid] ? expf(att_s[tid] - mx) : 0.f;
                alpha_s[tid] = e;
                red[tid] = e;
            }
            __syncthreads();
            for (int s = 64; s > 0; s >>= 1) {
                if (tid < s) red[tid] += red[tid + s];
                __syncthreads();
            }
            float dsum = red[0];
            float inv = (dsum > 0.f) ? 1.f / fmaxf(dsum, 1e-30f) : 0.f;
            __syncthreads();
            if (tid < KQ) alpha_s[tid] *= inv;
            __syncthreads();

            {
                int v = tid & (VDQ - 1), q = tid >> 7;
                const float* eb = enc + (size_t)b * KQ * VDQ;
                float s = 0.f;
                #pragma unroll 8
                for (int k = q * 64; k < q * 64 + 64; k++)
                    s += alpha_s[k] * __ldg(&eb[k * VDQ + v]);
                part[tid] = s;
            }
            __syncthreads();

            bool active = (t < lang_len[b]);
            if (tid < VDQ) {
                float aw = part[tid] + part[tid + 128];
                float gv = b_fbeta[tid];
                #pragma unroll
                for (int s = 0; s < NSPLIT; s++)
                    gv += __ldcg(&g_Yp[((size_t)s * BQ + b) * YDIM + 512 + tid]);
                __stcg(&g_awe[b * VDQ + tid], aw * sigf(gv));
                out_alpha[(size_t)b * TQ * KQ + (size_t)t * KQ + tid]
                    = active ? alpha_s[tid] : 0.f;
            }

            // fused Yhh partial reduction (same b)
            {
                int col = tid * 8;
                float4 s0 = make_float4(0.f, 0.f, 0.f, 0.f);
                float4 s1 = make_float4(0.f, 0.f, 0.f, 0.f);
                #pragma unroll
                for (int s = 0; s < NSPLIT; s++) {
                    const float* p = g_Yp + ((size_t)s * BQ + b) * YDIM + 640 + col;
                    float4 v0 = __ldcg((const float4*)p);
                    float4 v1 = __ldcg((const float4*)(p + 4));
                    s0.x += v0.x; s0.y += v0.y; s0.z += v0.z; s0.w += v0.w;
                    s1.x += v1.x; s1.y += v1.y; s1.z += v1.z; s1.w += v1.w;
                }
                __stcg((float4*)&g_Yhh[b * GN + col], s0);
                __stcg((float4*)&g_Yhh[b * GN + col + 4], s1);
            }
        }
        grid_bar((++round) * GRID_P);

        // ======================= P3: gates + LSTM (active batches only) ======
        int navail3 = __ldg(&g_ncnt[t]);
        if ((bid & 1) * 64 < navail3) {
            float* As  = (float*)sm;             // [16][64]
            float* Bs3 = (float*)(sm + 4096);    // [16][32]
            int m0 = (bid & 1) * 64;
            int jt = bid >> 1;
            int n0v = jt * 32;
            int am = tid >> 2, ak4 = (tid & 3) * 4;
            int vr = tid >> 3, kb = (tid & 7) * 2;
            int vcol = n0v + vr;
            int wr = (vcol & 3) * 512 + (vcol >> 2);
            const float* Brow = Wih + (size_t)wr * XDIM + EQ;

            int ai = m0 + am; if (ai >= navail3) ai = navail3 - 1;
            const float* Aw = g_awe + (size_t)__ldg(&g_border[ai]) * VDQ;

            int jx = tid & 7, my = tid >> 3;
            ull acc[2][2] = {{0ull, 0ull}, {0ull, 0ull}};

            float4 pa = __ldcg((const float4*)&Aw[ak4]);
            float2 pb = *(const float2*)&Brow[kb];

            for (int kt = 0; kt < 8; kt++) {
                As[(ak4 + 0) * 64 + am] = pa.x; As[(ak4 + 1) * 64 + am] = pa.y;
                As[(ak4 + 2) * 64 + am] = pa.z; As[(ak4 + 3) * 64 + am] = pa.w;
                Bs3[(kb + 0) * 32 + vr] = pb.x;
                Bs3[(kb + 1) * 32 + vr] = pb.y;
                __syncthreads();
                if (kt + 1 < 8) {
                    int k = (kt + 1) * 16;
                    pa = __ldcg((const float4*)&Aw[k + ak4]);
                    pb = *(const float2*)&Brow[k + kb];
                }
                #pragma unroll
                for (int kk = 0; kk < 16; kk++) {
                    float2 a2 = *(const float2*)&As[kk * 64 + my * 2];
                    const ull* bp = (const ull*)&Bs3[kk * 32 + jx * 4];
                    ull b01 = bp[0], b23 = bp[1];
                    ull pa0 = pk2(a2.x, a2.x), pa1 = pk2(a2.y, a2.y);
                    fma2(acc[0][0], pa0, b01); fma2(acc[0][1], pa0, b23);
                    fma2(acc[1][0], pa1, b01); fma2(acc[1][1], pa1, b23);
                }
                __syncthreads();
            }

            int j = jt * 8 + jx;
            float bi_i = b_ih[j]        + b_hh[j];
            float bi_f = b_ih[512 + j]  + b_hh[512 + j];
            float bi_g = b_ih[1024 + j] + b_hh[1024 + j];
            float bi_o = b_ih[1536 + j] + b_hh[1536 + j];
            #pragma unroll
            for (int i = 0; i < 2; i++) {
                int mi = m0 + my * 2 + i;
                if (mi >= navail3) continue;   // FIX: no duplicated RMW on c/h
                int b = __ldg(&g_border[mi]);
                const float* Gv = (t == 0) ? g_Ginit
                    : g_Gv + (size_t)__ldg(&lang_idx[b * TQ + (t - 1)]) * GN;
                float gi = lo32(acc[i][0]) + Gv[j]        + g_Gref[b * GN + j]        + __ldcg(&g_Yhh[b * GN + j])        + bi_i;
                float gf = hi32(acc[i][0]) + Gv[512 + j]  + g_Gref[b * GN + 512 + j]  + __ldcg(&g_Yhh[b * GN + 512 + j])  + bi_f;
                float gg = lo32(acc[i][1]) + Gv[1024 + j] + g_Gref[b * GN + 1024 + j] + __ldcg(&g_Yhh[b * GN + 1024 + j]) + bi_g;
                float go = hi32(acc[i][1]) + Gv[1536 + j] + g_Gref[b * GN + 1536 + j] + __ldcg(&g_Yhh[b * GN + 1536 + j]) + bi_o;
                float c_old = __ldcg(&g_c[b * DQ + j]);
                float cn = sigf(gf) * c_old + sigf(gi) * tanhf(gg);
                float hn = sigf(go) * tanhf(cn);
                // prefix guarantees t < lang_len[b]: always update
                __stcg(&g_c[b * DQ + j], cn);
                __stcg(&g_h[b * DQ + j], hn);
                g_hstore[((size_t)t * BQ + b) * DQ + j] = hn;
            }
        }
        if (t != TQ - 1) grid_bar((++round) * GRID_P);
    }

    // done protocol (reset counters for next graph replay)
    __syncthreads();
    __threadfence();
    if (tid == 0) {
        asm volatile("red.release.gpu.global.add.u32 [%0], %1;"
                     :: "l"(&g_done), "r"(1u) : "memory");
        if (bid == 0) {
            unsigned v;
            do {
                asm volatile("ld.acquire.gpu.global.u32 %0, [%1];"
                             : "=r"(v) : "l"(&g_done) : "memory");
            } while (v < (unsigned)GRID_P);
            asm volatile("st.global.cg.u32 [%0], %1;" :: "l"(&g_bar), "r"(0u) : "memory");
            __threadfence();
            asm volatile("st.release.gpu.global.u32 [%0], %1;"
                         :: "l"(&g_done), "r"(0u) : "memory");
        }
    }
}

// ---------- final: mask + transpose [T,B,V] -> [B,V,T] ------------------------
__global__ void transpose_preds(const int* __restrict__ lang_len,
                                float* __restrict__ out)
{
    __shared__ float tile[32][33];
    int b = blockIdx.x;
    int v0 = blockIdx.y * 32;
    int tx = threadIdx.x, ty = threadIdx.y;
    float s = 0.f;
    if (ty < lang_len[b])
        s = g_predsT[(size_t)ty * BQ * VQ + (size_t)b * VQ + v0 + tx];
    tile[ty][tx] = s;
    __syncthreads();
    out[(size_t)b * VQ * TQ + (size_t)(v0 + ty) * TQ + tx] = tile[tx][ty];
}

// ------------------------- launch ---------------------------------------------
extern "C" void kernel_launch(void* const* d_in, const int* in_sizes, int n_in,
                              void* d_out, int out_size)
{
    const float* enc       = (const float*)d_in[0];
    const float* ref_obj   = (const float*)d_in[1];
    const float* obj_sc    = (const float*)d_in[2];
    const float* center    = (const float*)d_in[3];
    const float* xyz       = (const float*)d_in[4];
    const int*   lang_idx  = (const int*)d_in[5];
    const int*   lang_len  = (const int*)d_in[6];
    const float* emb_tab   = (const float*)d_in[7];
    const float* init_emb  = (const float*)d_in[8];
    const float* W_enc_att = (const float*)d_in[9];
    const float* b_enc_att = (const float*)d_in[10];
    const float* W_dec_att = (const float*)d_in[11];
    const float* b_dec_att = (const float*)d_in[12];
    const float* w_full    = (const float*)d_in[13];
    const float* b_full    = (const float*)d_in[14];
    const float* W_ih      = (const float*)d_in[15];
    const float* b_ih      = (const float*)d_in[16];
    const float* W_hh      = (const float*)d_in[17];
    const float* b_hh      = (const float*)d_in[18];
    const float* W_init_h  = (const float*)d_in[19];
    const float* b_init_h  = (const float*)d_in[20];
    const float* W_init_c  = (const float*)d_in[21];
    const float* b_init_c  = (const float*)d_in[22];
    const float* W_fbeta   = (const float*)d_in[23];
    const float* b_fbeta   = (const float*)d_in[24];
    const float* W_fc      = (const float*)d_in[25];
    const float* b_fc      = (const float*)d_in[26];

    float* out       = (float*)d_out;
    float* out_alpha = out + (size_t)BQ * VQ * TQ;
    float* out_mask  = out_alpha + (size_t)BQ * TQ * KQ;

    float *p_att1, *p_Gv, *p_Gref, *p_hstore, *p_predsT;
    int *p_perm, *p_nact;
    cudaGetSymbolAddress((void**)&p_att1,   g_att1);
    cudaGetSymbolAddress((void**)&p_Gv,     g_Gv);
    cudaGetSymbolAddress((void**)&p_Gref,   g_Gref);
    cudaGetSymbolAddress((void**)&p_hstore, g_hstore);
    cudaGetSymbolAddress((void**)&p_predsT, g_predsT);
    cudaGetSymbolAddress((void**)&p_perm,   g_perm);
    cudaGetSymbolAddress((void**)&p_nact,   g_nact);

    fused_pre<<<265, 256>>>(obj_sc, center, xyz, enc, ref_obj, init_emb,
                            W_ih, lang_len, out_mask);
    init_hc<<<dim3(16, 4), 256>>>(W_init_h, b_init_h, W_init_c, b_init_c);
    gemm128<<<dim3(16, 1), 256>>>(ref_obj, ODQ, W_ih + EQ + VDQ, XDIM, nullptr,
                                  p_Gref, GN, BQ, GN, ODQ, nullptr, nullptr);
    gemm128<<<dim3(4, 128), 256>>>(enc, VDQ, W_enc_att, VDQ, b_enc_att,
                                   p_att1, AQ, BQ * KQ, AQ, VDQ, nullptr, nullptr);
    gemm128<<<dim3(16, 32), 256>>>(emb_tab, EQ, W_ih, XDIM, nullptr,
                                   p_Gv, GN, VQ, GN, EQ, nullptr, nullptr);
    decoder_loop<<<GRID_P, 256>>>(enc, W_dec_att, W_fbeta, W_hh,
                                  b_dec_att, b_fbeta, w_full, b_full,
                                  W_ih, b_ih, b_hh, lang_idx, lang_len,
                                  out_alpha);
    build_perm<<<1, 256>>>(lang_len);
    gemm128<<<dim3(32, 32), 256>>>(p_hstore, DQ, W_fc, DQ, b_fc,
                                   p_predsT, VQ, TQ * BQ, VQ, DQ, p_perm, p_nact);
    transpose_preds<<<dim3(BQ, VQ / 32), dim3(32, 32)>>>(lang_len, out);
}